// round 1
// baseline (speedup 1.0000x reference)
#include <cuda_runtime.h>
#include <cuda_bf16.h>
#include <cstdint>

#define N_NODES 100000
#define N_EDGES 1600000
#define D_FEAT  64
#define U1      128
#define U2      128

// Scratch (allocation-free rule: __device__ globals)
__device__ float g_AH [(size_t)N_NODES * D_FEAT];   // 25.6 MB
__device__ float g_H1 [(size_t)N_NODES * U1];       // 51.2 MB
__device__ float g_AH1[(size_t)N_NODES * U1];       // 51.2 MB

// ---------------------------------------------------------------------------
// zero kernel (float4 stores)
// ---------------------------------------------------------------------------
__global__ void zero_kernel(float4* __restrict__ p, int n4) {
    int i = blockIdx.x * blockDim.x + threadIdx.x;
    if (i < n4) p[i] = make_float4(0.f, 0.f, 0.f, 0.f);
}

// ---------------------------------------------------------------------------
// COO SpMM scatter: out[row[e], :] += vals[e] * H[col[e], :]
// One thread per (edge, group-of-4-features). Vector RED (no-return atomic).
// ---------------------------------------------------------------------------
__device__ __forceinline__ void red_add_v4(float* addr, float4 v) {
    asm volatile("red.global.add.v4.f32 [%0], {%1, %2, %3, %4};"
                 :: "l"(addr), "f"(v.x), "f"(v.y), "f"(v.z), "f"(v.w)
                 : "memory");
}

template <int FEAT>
__global__ void spmm_scatter(const int* __restrict__ row,
                             const int* __restrict__ col,
                             const float* __restrict__ vals,
                             const float* __restrict__ H,
                             float* __restrict__ out) {
    constexpr int G = FEAT / 4;              // float4 groups per row
    unsigned long long tid =
        (unsigned long long)blockIdx.x * blockDim.x + threadIdx.x;
    int e = (int)(tid / G);
    int g = (int)(tid % G);
    if (e >= N_EDGES) return;

    int   r = __ldg(row + e);
    int   c = __ldg(col + e);
    float v = __ldg(vals + e);

    const float4* hp = reinterpret_cast<const float4*>(H + (size_t)c * FEAT);
    float4 h = __ldg(hp + g);
    float4 p = make_float4(v * h.x, v * h.y, v * h.z, v * h.w);

    red_add_v4(out + (size_t)r * FEAT + 4 * g, p);
}

// ---------------------------------------------------------------------------
// GEMM + bias + ReLU:  out[N,128] = relu(A[N,K] @ W[K,128] + b)
// Block = 256 threads, tile = 64 rows x 128 cols.
//   thread (cx = tid&31, ry = tid>>5): 4 cols (float4) x 8 rows register tile.
// Full W and the 64-row A tile live in dynamic SMEM.
// ---------------------------------------------------------------------------
template <int K>
__global__ void gemm_bias_relu(const float* __restrict__ A,
                               const float* __restrict__ W,
                               const float* __restrict__ b,
                               float* __restrict__ out) {
    extern __shared__ float smem[];
    float* Ws = smem;             // K*128 floats
    float* As = smem + K * 128;   // 64*K  floats

    int tid = threadIdx.x;

    // load W (K x 128)
    const float4* W4 = reinterpret_cast<const float4*>(W);
    float4* Ws4v = reinterpret_cast<float4*>(Ws);
    #pragma unroll
    for (int i = tid; i < K * 32; i += 256) Ws4v[i] = W4[i];

    // load A tile (64 rows x K), zero-pad tail rows
    int row0 = blockIdx.x * 64;
    const float4* A4 = reinterpret_cast<const float4*>(A);
    float4* As4 = reinterpret_cast<float4*>(As);
    constexpr int K4 = K / 4;
    #pragma unroll
    for (int i = tid; i < 64 * K4; i += 256) {
        int r = row0 + i / K4;
        As4[i] = (r < N_NODES) ? __ldg(A4 + (size_t)r * K4 + (i % K4))
                               : make_float4(0.f, 0.f, 0.f, 0.f);
    }
    __syncthreads();

    int cx = tid & 31;   // column group: cols 4*cx .. 4*cx+3
    int ry = tid >> 5;   // row group: rows ry*8 .. ry*8+7

    float4 bias = reinterpret_cast<const float4*>(b)[cx];
    float4 acc[8];
    #pragma unroll
    for (int i = 0; i < 8; i++) acc[i] = bias;

    const float4* Ws4 = reinterpret_cast<const float4*>(Ws);
    const float* Arow = As + (ry * 8) * K;

    #pragma unroll 8
    for (int k = 0; k < K; k++) {
        float4 w = Ws4[k * 32 + cx];
        #pragma unroll
        for (int i = 0; i < 8; i++) {
            float a = Arow[i * K + k];   // warp-broadcast LDS
            acc[i].x = fmaf(a, w.x, acc[i].x);
            acc[i].y = fmaf(a, w.y, acc[i].y);
            acc[i].z = fmaf(a, w.z, acc[i].z);
            acc[i].w = fmaf(a, w.w, acc[i].w);
        }
    }

    #pragma unroll
    for (int i = 0; i < 8; i++) {
        int r = row0 + ry * 8 + i;
        if (r < N_NODES) {
            float4 o = make_float4(fmaxf(acc[i].x, 0.f), fmaxf(acc[i].y, 0.f),
                                   fmaxf(acc[i].z, 0.f), fmaxf(acc[i].w, 0.f));
            reinterpret_cast<float4*>(out + (size_t)r * 128)[cx] = o;
        }
    }
}

// ---------------------------------------------------------------------------
// launch
// ---------------------------------------------------------------------------
extern "C" void kernel_launch(void* const* d_in, const int* in_sizes, int n_in,
                              void* d_out, int out_size) {
    const int*   row  = (const int*)  d_in[0];
    const int*   col  = (const int*)  d_in[1];
    const float* vals = (const float*)d_in[2];
    const float* H    = (const float*)d_in[3];
    const float* W1   = (const float*)d_in[4];
    const float* b1   = (const float*)d_in[5];
    const float* W2   = (const float*)d_in[6];
    const float* b2   = (const float*)d_in[7];
    float* out = (float*)d_out;

    void *pAH_, *pH1_, *pAH1_;
    cudaGetSymbolAddress(&pAH_,  g_AH);
    cudaGetSymbolAddress(&pH1_,  g_H1);
    cudaGetSymbolAddress(&pAH1_, g_AH1);
    float* pAH  = (float*)pAH_;
    float* pH1  = (float*)pH1_;
    float* pAH1 = (float*)pAH1_;

    // opt-in to >48KB dynamic smem for the GEMMs (idempotent, host-side only)
    cudaFuncSetAttribute(gemm_bias_relu<64>,
                         cudaFuncAttributeMaxDynamicSharedMemorySize,
                         (64 * 128 + 64 * 64) * 4);
    cudaFuncSetAttribute(gemm_bias_relu<128>,
                         cudaFuncAttributeMaxDynamicSharedMemorySize,
                         (128 * 128 + 64 * 128) * 4);

    // zero scatter targets
    {
        int n4a = N_NODES * D_FEAT / 4;
        int n4b = N_NODES * U1 / 4;
        zero_kernel<<<(n4a + 255) / 256, 256>>>((float4*)pAH,  n4a);
        zero_kernel<<<(n4b + 255) / 256, 256>>>((float4*)pAH1, n4b);
    }

    // layer 0: AH = A @ H ; H1 = relu(AH @ W1 + b1)
    {
        unsigned long long tot = (unsigned long long)N_EDGES * (D_FEAT / 4);
        int blocks = (int)((tot + 255) / 256);
        spmm_scatter<D_FEAT><<<blocks, 256>>>(row, col, vals, H, pAH);

        int gblocks = (N_NODES + 63) / 64;
        gemm_bias_relu<64><<<gblocks, 256, (64 * 128 + 64 * 64) * 4>>>(
            pAH, W1, b1, pH1);
    }

    // layer 1: AH1 = A @ H1 ; out = relu(AH1 @ W2 + b2)
    {
        unsigned long long tot = (unsigned long long)N_EDGES * (U1 / 4);
        int blocks = (int)((tot + 255) / 256);
        spmm_scatter<U1><<<blocks, 256>>>(row, col, vals, pH1, pAH1);

        int gblocks = (N_NODES + 63) / 64;
        gemm_bias_relu<128><<<gblocks, 256, (128 * 128 + 64 * 128) * 4>>>(
            pAH1, W2, b2, out);
    }
}

// round 2
// speedup vs baseline: 1.0614x; 1.0614x over previous
#include <cuda_runtime.h>
#include <cuda_bf16.h>
#include <cstdint>

#define N_NODES 100000
#define N_EDGES 1600000
#define D_FEAT  64
#define U1      128
#define U2      128

// ---------------------------------------------------------------------------
// Scratch (allocation-free rule: __device__ globals)
// ---------------------------------------------------------------------------
__device__ float g_AH [(size_t)N_NODES * D_FEAT];   // 25.6 MB
__device__ float g_H1 [(size_t)N_NODES * U1];       // 51.2 MB
__device__ float g_AH1[(size_t)N_NODES * U1];       // 51.2 MB
__device__ int   g_counts[N_NODES];
__device__ int   g_rowptr[N_NODES + 1];
__device__ int   g_tmp   [N_NODES];
__device__ int   g_csr_col[N_EDGES];                // 6.4 MB
__device__ float g_csr_val[N_EDGES];                // 6.4 MB

// ---------------------------------------------------------------------------
// CSR build: zero counts -> histogram -> single-block scan -> scatter
// ---------------------------------------------------------------------------
__global__ void zero_counts_kernel(int* __restrict__ counts) {
    int i = blockIdx.x * blockDim.x + threadIdx.x;
    if (i < N_NODES) counts[i] = 0;
}

__global__ void hist_kernel(const int* __restrict__ row, int* __restrict__ counts) {
    int e = blockIdx.x * blockDim.x + threadIdx.x;
    if (e < N_EDGES) atomicAdd(&counts[row[e]], 1);   // spread-addr RED
}

// single block, 1024 threads: exclusive scan of counts -> rowptr & tmp
__global__ void scan_kernel(const int* __restrict__ counts,
                            int* __restrict__ rowptr,
                            int* __restrict__ tmp) {
    __shared__ int partial[1024];
    const int tid = threadIdx.x;
    const int CH = (N_NODES + 1023) / 1024;           // 98
    int beg = tid * CH;
    int end = beg + CH; if (end > N_NODES) end = N_NODES;
    if (beg > N_NODES) beg = N_NODES;

    int s = 0;
    for (int i = beg; i < end; i++) s += counts[i];
    partial[tid] = s;
    __syncthreads();

    // Hillis-Steele inclusive scan in smem
    for (int off = 1; off < 1024; off <<= 1) {
        int v = 0;
        if (tid >= off) v = partial[tid - off];
        __syncthreads();
        if (tid >= off) partial[tid] += v;
        __syncthreads();
    }
    int run = (tid == 0) ? 0 : partial[tid - 1];      // exclusive prefix

    for (int i = beg; i < end; i++) {
        rowptr[i] = run;
        tmp[i]    = run;
        run += counts[i];
    }
    if (tid == 1023) rowptr[N_NODES] = run;           // == N_EDGES
}

// permuted-value scatter: edge payload goes to CSR order (kills one indirection)
__global__ void build_csr_kernel(const int* __restrict__ row,
                                 const int* __restrict__ col,
                                 const float* __restrict__ vals,
                                 int* __restrict__ tmp,
                                 int* __restrict__ csr_col,
                                 float* __restrict__ csr_val) {
    int e = blockIdx.x * blockDim.x + threadIdx.x;
    if (e >= N_EDGES) return;
    int p = atomicAdd(&tmp[row[e]], 1);
    csr_col[p] = col[e];
    csr_val[p] = vals[e];
}

// ---------------------------------------------------------------------------
// Gather SpMM: one warp per output row, no atomics.
//   FEAT=128: lane holds float4 (cols 4*lane..4*lane+3)
//   FEAT=64 : lane holds float2
// Edge loop unrolled by 4 for MLP on the H gathers.
// ---------------------------------------------------------------------------
__global__ void spmm_gather128(const int* __restrict__ rowptr,
                               const int* __restrict__ csr_col,
                               const float* __restrict__ csr_val,
                               const float* __restrict__ H,
                               float* __restrict__ out) {
    int warp = (blockIdx.x * blockDim.x + threadIdx.x) >> 5;
    int lane = threadIdx.x & 31;
    if (warp >= N_NODES) return;

    int beg = __ldg(rowptr + warp);
    int end = __ldg(rowptr + warp + 1);

    const float4* H4 = reinterpret_cast<const float4*>(H);
    float4 acc = make_float4(0.f, 0.f, 0.f, 0.f);

    int e = beg;
    for (; e + 4 <= end; e += 4) {
        int   c0 = __ldg(csr_col + e + 0), c1 = __ldg(csr_col + e + 1);
        int   c2 = __ldg(csr_col + e + 2), c3 = __ldg(csr_col + e + 3);
        float v0 = __ldg(csr_val + e + 0), v1 = __ldg(csr_val + e + 1);
        float v2 = __ldg(csr_val + e + 2), v3 = __ldg(csr_val + e + 3);
        float4 h0 = __ldg(H4 + (size_t)c0 * 32 + lane);
        float4 h1 = __ldg(H4 + (size_t)c1 * 32 + lane);
        float4 h2 = __ldg(H4 + (size_t)c2 * 32 + lane);
        float4 h3 = __ldg(H4 + (size_t)c3 * 32 + lane);
        acc.x = fmaf(v0, h0.x, acc.x); acc.y = fmaf(v0, h0.y, acc.y);
        acc.z = fmaf(v0, h0.z, acc.z); acc.w = fmaf(v0, h0.w, acc.w);
        acc.x = fmaf(v1, h1.x, acc.x); acc.y = fmaf(v1, h1.y, acc.y);
        acc.z = fmaf(v1, h1.z, acc.z); acc.w = fmaf(v1, h1.w, acc.w);
        acc.x = fmaf(v2, h2.x, acc.x); acc.y = fmaf(v2, h2.y, acc.y);
        acc.z = fmaf(v2, h2.z, acc.z); acc.w = fmaf(v2, h2.w, acc.w);
        acc.x = fmaf(v3, h3.x, acc.x); acc.y = fmaf(v3, h3.y, acc.y);
        acc.z = fmaf(v3, h3.z, acc.z); acc.w = fmaf(v3, h3.w, acc.w);
    }
    for (; e < end; e++) {
        int   c = __ldg(csr_col + e);
        float v = __ldg(csr_val + e);
        float4 h = __ldg(H4 + (size_t)c * 32 + lane);
        acc.x = fmaf(v, h.x, acc.x); acc.y = fmaf(v, h.y, acc.y);
        acc.z = fmaf(v, h.z, acc.z); acc.w = fmaf(v, h.w, acc.w);
    }
    reinterpret_cast<float4*>(out)[(size_t)warp * 32 + lane] = acc;
}

__global__ void spmm_gather64(const int* __restrict__ rowptr,
                              const int* __restrict__ csr_col,
                              const float* __restrict__ csr_val,
                              const float* __restrict__ H,
                              float* __restrict__ out) {
    int warp = (blockIdx.x * blockDim.x + threadIdx.x) >> 5;
    int lane = threadIdx.x & 31;
    if (warp >= N_NODES) return;

    int beg = __ldg(rowptr + warp);
    int end = __ldg(rowptr + warp + 1);

    const float2* H2 = reinterpret_cast<const float2*>(H);
    float2 acc = make_float2(0.f, 0.f);

    int e = beg;
    for (; e + 4 <= end; e += 4) {
        int   c0 = __ldg(csr_col + e + 0), c1 = __ldg(csr_col + e + 1);
        int   c2 = __ldg(csr_col + e + 2), c3 = __ldg(csr_col + e + 3);
        float v0 = __ldg(csr_val + e + 0), v1 = __ldg(csr_val + e + 1);
        float v2 = __ldg(csr_val + e + 2), v3 = __ldg(csr_val + e + 3);
        float2 h0 = __ldg(H2 + (size_t)c0 * 32 + lane);
        float2 h1 = __ldg(H2 + (size_t)c1 * 32 + lane);
        float2 h2 = __ldg(H2 + (size_t)c2 * 32 + lane);
        float2 h3 = __ldg(H2 + (size_t)c3 * 32 + lane);
        acc.x = fmaf(v0, h0.x, acc.x); acc.y = fmaf(v0, h0.y, acc.y);
        acc.x = fmaf(v1, h1.x, acc.x); acc.y = fmaf(v1, h1.y, acc.y);
        acc.x = fmaf(v2, h2.x, acc.x); acc.y = fmaf(v2, h2.y, acc.y);
        acc.x = fmaf(v3, h3.x, acc.x); acc.y = fmaf(v3, h3.y, acc.y);
    }
    for (; e < end; e++) {
        int   c = __ldg(csr_col + e);
        float v = __ldg(csr_val + e);
        float2 h = __ldg(H2 + (size_t)c * 32 + lane);
        acc.x = fmaf(v, h.x, acc.x); acc.y = fmaf(v, h.y, acc.y);
    }
    reinterpret_cast<float2*>(out)[(size_t)warp * 32 + lane] = acc;
}

// ---------------------------------------------------------------------------
// GEMM + bias + ReLU:  out[N,128] = relu(A[N,K] @ W[K,128] + b)
// (unchanged from R1 — 64-row x 128-col block tile, 4x8 register tile)
// ---------------------------------------------------------------------------
template <int K>
__global__ void gemm_bias_relu(const float* __restrict__ A,
                               const float* __restrict__ W,
                               const float* __restrict__ b,
                               float* __restrict__ out) {
    extern __shared__ float smem[];
    float* Ws = smem;             // K*128 floats
    float* As = smem + K * 128;   // 64*K  floats

    int tid = threadIdx.x;

    const float4* W4 = reinterpret_cast<const float4*>(W);
    float4* Ws4v = reinterpret_cast<float4*>(Ws);
    #pragma unroll
    for (int i = tid; i < K * 32; i += 256) Ws4v[i] = W4[i];

    int row0 = blockIdx.x * 64;
    const float4* A4 = reinterpret_cast<const float4*>(A);
    float4* As4 = reinterpret_cast<float4*>(As);
    constexpr int K4 = K / 4;
    #pragma unroll
    for (int i = tid; i < 64 * K4; i += 256) {
        int r = row0 + i / K4;
        As4[i] = (r < N_NODES) ? __ldg(A4 + (size_t)r * K4 + (i % K4))
                               : make_float4(0.f, 0.f, 0.f, 0.f);
    }
    __syncthreads();

    int cx = tid & 31;
    int ry = tid >> 5;

    float4 bias = reinterpret_cast<const float4*>(b)[cx];
    float4 acc[8];
    #pragma unroll
    for (int i = 0; i < 8; i++) acc[i] = bias;

    const float4* Ws4 = reinterpret_cast<const float4*>(Ws);
    const float* Arow = As + (ry * 8) * K;

    #pragma unroll 8
    for (int k = 0; k < K; k++) {
        float4 w = Ws4[k * 32 + cx];
        #pragma unroll
        for (int i = 0; i < 8; i++) {
            float a = Arow[i * K + k];
            acc[i].x = fmaf(a, w.x, acc[i].x);
            acc[i].y = fmaf(a, w.y, acc[i].y);
            acc[i].z = fmaf(a, w.z, acc[i].z);
            acc[i].w = fmaf(a, w.w, acc[i].w);
        }
    }

    #pragma unroll
    for (int i = 0; i < 8; i++) {
        int r = row0 + ry * 8 + i;
        if (r < N_NODES) {
            float4 o = make_float4(fmaxf(acc[i].x, 0.f), fmaxf(acc[i].y, 0.f),
                                   fmaxf(acc[i].z, 0.f), fmaxf(acc[i].w, 0.f));
            reinterpret_cast<float4*>(out + (size_t)r * 128)[cx] = o;
        }
    }
}

// ---------------------------------------------------------------------------
// launch
// ---------------------------------------------------------------------------
extern "C" void kernel_launch(void* const* d_in, const int* in_sizes, int n_in,
                              void* d_out, int out_size) {
    const int*   row  = (const int*)  d_in[0];
    const int*   col  = (const int*)  d_in[1];
    const float* vals = (const float*)d_in[2];
    const float* H    = (const float*)d_in[3];
    const float* W1   = (const float*)d_in[4];
    const float* b1   = (const float*)d_in[5];
    const float* W2   = (const float*)d_in[6];
    const float* b2   = (const float*)d_in[7];
    float* out = (float*)d_out;

    void *pAH_, *pH1_, *pAH1_, *pCnt_, *pRp_, *pTmp_, *pCc_, *pCv_;
    cudaGetSymbolAddress(&pAH_,  g_AH);
    cudaGetSymbolAddress(&pH1_,  g_H1);
    cudaGetSymbolAddress(&pAH1_, g_AH1);
    cudaGetSymbolAddress(&pCnt_, g_counts);
    cudaGetSymbolAddress(&pRp_,  g_rowptr);
    cudaGetSymbolAddress(&pTmp_, g_tmp);
    cudaGetSymbolAddress(&pCc_,  g_csr_col);
    cudaGetSymbolAddress(&pCv_,  g_csr_val);
    float* pAH  = (float*)pAH_;
    float* pH1  = (float*)pH1_;
    float* pAH1 = (float*)pAH1_;
    int*   pCnt = (int*)pCnt_;
    int*   pRp  = (int*)pRp_;
    int*   pTmp = (int*)pTmp_;
    int*   pCc  = (int*)pCc_;
    float* pCv  = (float*)pCv_;

    cudaFuncSetAttribute(gemm_bias_relu<64>,
                         cudaFuncAttributeMaxDynamicSharedMemorySize,
                         (64 * 128 + 64 * 64) * 4);
    cudaFuncSetAttribute(gemm_bias_relu<128>,
                         cudaFuncAttributeMaxDynamicSharedMemorySize,
                         (128 * 128 + 64 * 128) * 4);

    // ---- CSR build (amortized over both layers)
    zero_counts_kernel<<<(N_NODES + 255) / 256, 256>>>(pCnt);
    hist_kernel<<<(N_EDGES + 255) / 256, 256>>>(row, pCnt);
    scan_kernel<<<1, 1024>>>(pCnt, pRp, pTmp);
    build_csr_kernel<<<(N_EDGES + 255) / 256, 256>>>(row, col, vals, pTmp, pCc, pCv);

    const int warps_grid = (N_NODES * 32 + 255) / 256;   // 1 warp per row
    const int gblocks = (N_NODES + 63) / 64;

    // ---- layer 0
    spmm_gather64<<<warps_grid, 256>>>(pRp, pCc, pCv, H, pAH);
    gemm_bias_relu<64><<<gblocks, 256, (64 * 128 + 64 * 64) * 4>>>(pAH, W1, b1, pH1);

    // ---- layer 1
    spmm_gather128<<<warps_grid, 256>>>(pRp, pCc, pCv, pH1, pAH1);
    gemm_bias_relu<128><<<gblocks, 256, (128 * 128 + 64 * 128) * 4>>>(pAH1, W2, b2, out);
}

// round 3
// speedup vs baseline: 1.1948x; 1.1257x over previous
#include <cuda_runtime.h>
#include <cuda_bf16.h>
#include <cstdint>

#define N_NODES 100000
#define N_EDGES 1600000
#define D_FEAT  64
#define U1      128
#define U2      128

// ---------------------------------------------------------------------------
// Scratch (allocation-free rule: __device__ globals)
// ---------------------------------------------------------------------------
__device__ float g_AH [(size_t)N_NODES * D_FEAT];   // 25.6 MB
__device__ float g_H1 [(size_t)N_NODES * U1];       // 51.2 MB
__device__ float g_AH1[(size_t)N_NODES * U1];       // 51.2 MB
__device__ int   g_counts[N_NODES];
__device__ int   g_rowptr[N_NODES + 1];
__device__ int   g_localoff[N_EDGES];               // 6.4 MB
__device__ int4  g_csr_cv[N_EDGES / 2];             // packed (col,val) pairs, 12.8 MB

// ---------------------------------------------------------------------------
// CSR build
// ---------------------------------------------------------------------------
// pass 1: histogram + per-edge local offset (the ONLY atomic pass)
__global__ void hist_off_kernel(const int* __restrict__ row,
                                int* __restrict__ counts,
                                int* __restrict__ localoff) {
    int e = blockIdx.x * blockDim.x + threadIdx.x;
    if (e < N_EDGES) localoff[e] = atomicAdd(&counts[row[e]], 1);
}

// pass 2: single-block warp-shuffle exclusive scan -> rowptr
__global__ void scan_kernel(const int* __restrict__ counts,
                            int* __restrict__ rowptr) {
    const int tid  = threadIdx.x;
    const int lane = tid & 31;
    const int wid  = tid >> 5;
    const int CH   = (N_NODES + 1023) / 1024;        // 98
    int beg = tid * CH;
    int end = beg + CH; if (end > N_NODES) end = N_NODES;
    if (beg > N_NODES) beg = N_NODES;

    int s = 0;
    for (int i = beg; i < end; i++) s += counts[i];

    // warp inclusive scan
    int v = s;
    #pragma unroll
    for (int o = 1; o < 32; o <<= 1) {
        int t = __shfl_up_sync(0xFFFFFFFFu, v, o);
        if (lane >= o) v += t;
    }
    __shared__ int wsum[32];
    if (lane == 31) wsum[wid] = v;
    __syncthreads();
    if (wid == 0) {
        int x = wsum[lane];
        #pragma unroll
        for (int o = 1; o < 32; o <<= 1) {
            int t = __shfl_up_sync(0xFFFFFFFFu, x, o);
            if (lane >= o) x += t;
        }
        wsum[lane] = x;
    }
    __syncthreads();
    int incl = v + (wid > 0 ? wsum[wid - 1] : 0);
    int run  = incl - s;                              // exclusive prefix

    for (int i = beg; i < end; i++) {
        rowptr[i] = run;
        run += counts[i];
    }
    if (tid == 1023) rowptr[N_NODES] = run;           // == N_EDGES
}

// pass 3: atomic-free scatter of packed (col, val) payload into CSR order
__global__ void build_csr_kernel(const int* __restrict__ row,
                                 const int* __restrict__ col,
                                 const float* __restrict__ vals,
                                 const int* __restrict__ localoff,
                                 const int* __restrict__ rowptr,
                                 int2* __restrict__ cv) {
    int e = blockIdx.x * blockDim.x + threadIdx.x;
    if (e >= N_EDGES) return;
    int p = __ldg(rowptr + row[e]) + localoff[e];
    cv[p] = make_int2(col[e], __float_as_int(vals[e]));
}

// ---------------------------------------------------------------------------
// Gather SpMM: one warp per output row, no atomics, packed int2 payload,
// edge unroll 8 via aligned int4 loads (4 metadata LDG + 8 gathers / 8 edges).
// ---------------------------------------------------------------------------
__global__ void spmm_gather128(const int* __restrict__ rowptr,
                               const int2* __restrict__ cv,
                               const float* __restrict__ H,
                               float* __restrict__ out) {
    int warp = (blockIdx.x * blockDim.x + threadIdx.x) >> 5;
    int lane = threadIdx.x & 31;
    if (warp >= N_NODES) return;

    int beg = __ldg(rowptr + warp);
    int end = __ldg(rowptr + warp + 1);

    const float4* H4 = reinterpret_cast<const float4*>(H);
    float4 acc = make_float4(0.f, 0.f, 0.f, 0.f);

    int e = beg;
    // align e to even for int4 loads
    if ((e & 1) && e < end) {
        int2 p = __ldg(cv + e);
        float v = __int_as_float(p.y);
        float4 h = __ldg(H4 + (size_t)p.x * 32 + lane);
        acc.x = fmaf(v, h.x, acc.x); acc.y = fmaf(v, h.y, acc.y);
        acc.z = fmaf(v, h.z, acc.z); acc.w = fmaf(v, h.w, acc.w);
        e++;
    }
    const int4* CV4 = reinterpret_cast<const int4*>(cv);
    for (; e + 8 <= end; e += 8) {
        int4 q0 = __ldg(CV4 + (e >> 1) + 0);
        int4 q1 = __ldg(CV4 + (e >> 1) + 1);
        int4 q2 = __ldg(CV4 + (e >> 1) + 2);
        int4 q3 = __ldg(CV4 + (e >> 1) + 3);
        float4 h0 = __ldg(H4 + (size_t)q0.x * 32 + lane);
        float4 h1 = __ldg(H4 + (size_t)q0.z * 32 + lane);
        float4 h2 = __ldg(H4 + (size_t)q1.x * 32 + lane);
        float4 h3 = __ldg(H4 + (size_t)q1.z * 32 + lane);
        float4 h4 = __ldg(H4 + (size_t)q2.x * 32 + lane);
        float4 h5 = __ldg(H4 + (size_t)q2.z * 32 + lane);
        float4 h6 = __ldg(H4 + (size_t)q3.x * 32 + lane);
        float4 h7 = __ldg(H4 + (size_t)q3.z * 32 + lane);
        float v0 = __int_as_float(q0.y), v1 = __int_as_float(q0.w);
        float v2 = __int_as_float(q1.y), v3 = __int_as_float(q1.w);
        float v4 = __int_as_float(q2.y), v5 = __int_as_float(q2.w);
        float v6 = __int_as_float(q3.y), v7 = __int_as_float(q3.w);
        acc.x = fmaf(v0, h0.x, acc.x); acc.y = fmaf(v0, h0.y, acc.y);
        acc.z = fmaf(v0, h0.z, acc.z); acc.w = fmaf(v0, h0.w, acc.w);
        acc.x = fmaf(v1, h1.x, acc.x); acc.y = fmaf(v1, h1.y, acc.y);
        acc.z = fmaf(v1, h1.z, acc.z); acc.w = fmaf(v1, h1.w, acc.w);
        acc.x = fmaf(v2, h2.x, acc.x); acc.y = fmaf(v2, h2.y, acc.y);
        acc.z = fmaf(v2, h2.z, acc.z); acc.w = fmaf(v2, h2.w, acc.w);
        acc.x = fmaf(v3, h3.x, acc.x); acc.y = fmaf(v3, h3.y, acc.y);
        acc.z = fmaf(v3, h3.z, acc.z); acc.w = fmaf(v3, h3.w, acc.w);
        acc.x = fmaf(v4, h4.x, acc.x); acc.y = fmaf(v4, h4.y, acc.y);
        acc.z = fmaf(v4, h4.z, acc.z); acc.w = fmaf(v4, h4.w, acc.w);
        acc.x = fmaf(v5, h5.x, acc.x); acc.y = fmaf(v5, h5.y, acc.y);
        acc.z = fmaf(v5, h5.z, acc.z); acc.w = fmaf(v5, h5.w, acc.w);
        acc.x = fmaf(v6, h6.x, acc.x); acc.y = fmaf(v6, h6.y, acc.y);
        acc.z = fmaf(v6, h6.z, acc.z); acc.w = fmaf(v6, h6.w, acc.w);
        acc.x = fmaf(v7, h7.x, acc.x); acc.y = fmaf(v7, h7.y, acc.y);
        acc.z = fmaf(v7, h7.z, acc.z); acc.w = fmaf(v7, h7.w, acc.w);
    }
    for (; e + 2 <= end; e += 2) {
        int4 q = __ldg(CV4 + (e >> 1));
        float4 h0 = __ldg(H4 + (size_t)q.x * 32 + lane);
        float4 h1 = __ldg(H4 + (size_t)q.z * 32 + lane);
        float v0 = __int_as_float(q.y), v1 = __int_as_float(q.w);
        acc.x = fmaf(v0, h0.x, acc.x); acc.y = fmaf(v0, h0.y, acc.y);
        acc.z = fmaf(v0, h0.z, acc.z); acc.w = fmaf(v0, h0.w, acc.w);
        acc.x = fmaf(v1, h1.x, acc.x); acc.y = fmaf(v1, h1.y, acc.y);
        acc.z = fmaf(v1, h1.z, acc.z); acc.w = fmaf(v1, h1.w, acc.w);
    }
    if (e < end) {
        int2 p = __ldg(cv + e);
        float v = __int_as_float(p.y);
        float4 h = __ldg(H4 + (size_t)p.x * 32 + lane);
        acc.x = fmaf(v, h.x, acc.x); acc.y = fmaf(v, h.y, acc.y);
        acc.z = fmaf(v, h.z, acc.z); acc.w = fmaf(v, h.w, acc.w);
    }
    reinterpret_cast<float4*>(out)[(size_t)warp * 32 + lane] = acc;
}

__global__ void spmm_gather64(const int* __restrict__ rowptr,
                              const int2* __restrict__ cv,
                              const float* __restrict__ H,
                              float* __restrict__ out) {
    int warp = (blockIdx.x * blockDim.x + threadIdx.x) >> 5;
    int lane = threadIdx.x & 31;
    if (warp >= N_NODES) return;

    int beg = __ldg(rowptr + warp);
    int end = __ldg(rowptr + warp + 1);

    const float2* H2 = reinterpret_cast<const float2*>(H);
    float2 acc = make_float2(0.f, 0.f);

    int e = beg;
    if ((e & 1) && e < end) {
        int2 p = __ldg(cv + e);
        float v = __int_as_float(p.y);
        float2 h = __ldg(H2 + (size_t)p.x * 32 + lane);
        acc.x = fmaf(v, h.x, acc.x); acc.y = fmaf(v, h.y, acc.y);
        e++;
    }
    const int4* CV4 = reinterpret_cast<const int4*>(cv);
    for (; e + 8 <= end; e += 8) {
        int4 q0 = __ldg(CV4 + (e >> 1) + 0);
        int4 q1 = __ldg(CV4 + (e >> 1) + 1);
        int4 q2 = __ldg(CV4 + (e >> 1) + 2);
        int4 q3 = __ldg(CV4 + (e >> 1) + 3);
        float2 h0 = __ldg(H2 + (size_t)q0.x * 32 + lane);
        float2 h1 = __ldg(H2 + (size_t)q0.z * 32 + lane);
        float2 h2 = __ldg(H2 + (size_t)q1.x * 32 + lane);
        float2 h3 = __ldg(H2 + (size_t)q1.z * 32 + lane);
        float2 h4 = __ldg(H2 + (size_t)q2.x * 32 + lane);
        float2 h5 = __ldg(H2 + (size_t)q2.z * 32 + lane);
        float2 h6 = __ldg(H2 + (size_t)q3.x * 32 + lane);
        float2 h7 = __ldg(H2 + (size_t)q3.z * 32 + lane);
        float v0 = __int_as_float(q0.y), v1 = __int_as_float(q0.w);
        float v2 = __int_as_float(q1.y), v3 = __int_as_float(q1.w);
        float v4 = __int_as_float(q2.y), v5 = __int_as_float(q2.w);
        float v6 = __int_as_float(q3.y), v7 = __int_as_float(q3.w);
        acc.x = fmaf(v0, h0.x, acc.x); acc.y = fmaf(v0, h0.y, acc.y);
        acc.x = fmaf(v1, h1.x, acc.x); acc.y = fmaf(v1, h1.y, acc.y);
        acc.x = fmaf(v2, h2.x, acc.x); acc.y = fmaf(v2, h2.y, acc.y);
        acc.x = fmaf(v3, h3.x, acc.x); acc.y = fmaf(v3, h3.y, acc.y);
        acc.x = fmaf(v4, h4.x, acc.x); acc.y = fmaf(v4, h4.y, acc.y);
        acc.x = fmaf(v5, h5.x, acc.x); acc.y = fmaf(v5, h5.y, acc.y);
        acc.x = fmaf(v6, h6.x, acc.x); acc.y = fmaf(v6, h6.y, acc.y);
        acc.x = fmaf(v7, h7.x, acc.x); acc.y = fmaf(v7, h7.y, acc.y);
    }
    for (; e + 2 <= end; e += 2) {
        int4 q = __ldg(CV4 + (e >> 1));
        float2 h0 = __ldg(H2 + (size_t)q.x * 32 + lane);
        float2 h1 = __ldg(H2 + (size_t)q.z * 32 + lane);
        float v0 = __int_as_float(q.y), v1 = __int_as_float(q.w);
        acc.x = fmaf(v0, h0.x, acc.x); acc.y = fmaf(v0, h0.y, acc.y);
        acc.x = fmaf(v1, h1.x, acc.x); acc.y = fmaf(v1, h1.y, acc.y);
    }
    if (e < end) {
        int2 p = __ldg(cv + e);
        float v = __int_as_float(p.y);
        float2 h = __ldg(H2 + (size_t)p.x * 32 + lane);
        acc.x = fmaf(v, h.x, acc.x); acc.y = fmaf(v, h.y, acc.y);
    }
    reinterpret_cast<float2*>(out)[(size_t)warp * 32 + lane] = acc;
}

// ---------------------------------------------------------------------------
// GEMM + bias + ReLU:  out[N,128] = relu(A[N,K] @ W[K,128] + b)
// 64-row x 128-col block tile; thread = 8 rows x 4 cols; k unrolled x4 with
// float4 A loads: 12 LDS.128 per 128 FFMA.
// ---------------------------------------------------------------------------
template <int K>
__global__ void gemm_bias_relu(const float* __restrict__ A,
                               const float* __restrict__ W,
                               const float* __restrict__ b,
                               float* __restrict__ out) {
    extern __shared__ float smem[];
    float* Ws = smem;             // K*128 floats
    float* As = smem + K * 128;   // 64*K  floats

    int tid = threadIdx.x;

    const float4* W4 = reinterpret_cast<const float4*>(W);
    float4* Ws4v = reinterpret_cast<float4*>(Ws);
    #pragma unroll
    for (int i = tid; i < K * 32; i += 256) Ws4v[i] = W4[i];

    int row0 = blockIdx.x * 64;
    const float4* A4 = reinterpret_cast<const float4*>(A);
    float4* As4 = reinterpret_cast<float4*>(As);
    constexpr int K4 = K / 4;
    #pragma unroll
    for (int i = tid; i < 64 * K4; i += 256) {
        int r = row0 + i / K4;
        As4[i] = (r < N_NODES) ? __ldg(A4 + (size_t)r * K4 + (i % K4))
                               : make_float4(0.f, 0.f, 0.f, 0.f);
    }
    __syncthreads();

    int cx = tid & 31;
    int ry = tid >> 5;

    float4 bias = reinterpret_cast<const float4*>(b)[cx];
    float4 acc[8];
    #pragma unroll
    for (int i = 0; i < 8; i++) acc[i] = bias;

    const float4* Ws4 = reinterpret_cast<const float4*>(Ws);
    const float4* Atile = reinterpret_cast<const float4*>(As) + (ry * 8) * K4;

    #pragma unroll
    for (int k = 0; k < K; k += 4) {
        float4 w0 = Ws4[(k + 0) * 32 + cx];
        float4 w1 = Ws4[(k + 1) * 32 + cx];
        float4 w2 = Ws4[(k + 2) * 32 + cx];
        float4 w3 = Ws4[(k + 3) * 32 + cx];
        #pragma unroll
        for (int i = 0; i < 8; i++) {
            float4 a = Atile[i * K4 + (k >> 2)];
            acc[i].x = fmaf(a.x, w0.x, acc[i].x);
            acc[i].y = fmaf(a.x, w0.y, acc[i].y);
            acc[i].z = fmaf(a.x, w0.z, acc[i].z);
            acc[i].w = fmaf(a.x, w0.w, acc[i].w);
            acc[i].x = fmaf(a.y, w1.x, acc[i].x);
            acc[i].y = fmaf(a.y, w1.y, acc[i].y);
            acc[i].z = fmaf(a.y, w1.z, acc[i].z);
            acc[i].w = fmaf(a.y, w1.w, acc[i].w);
            acc[i].x = fmaf(a.z, w2.x, acc[i].x);
            acc[i].y = fmaf(a.z, w2.y, acc[i].y);
            acc[i].z = fmaf(a.z, w2.z, acc[i].z);
            acc[i].w = fmaf(a.z, w2.w, acc[i].w);
            acc[i].x = fmaf(a.w, w3.x, acc[i].x);
            acc[i].y = fmaf(a.w, w3.y, acc[i].y);
            acc[i].z = fmaf(a.w, w3.z, acc[i].z);
            acc[i].w = fmaf(a.w, w3.w, acc[i].w);
        }
    }

    #pragma unroll
    for (int i = 0; i < 8; i++) {
        int r = row0 + ry * 8 + i;
        if (r < N_NODES) {
            float4 o = make_float4(fmaxf(acc[i].x, 0.f), fmaxf(acc[i].y, 0.f),
                                   fmaxf(acc[i].z, 0.f), fmaxf(acc[i].w, 0.f));
            reinterpret_cast<float4*>(out + (size_t)r * 128)[cx] = o;
        }
    }
}

// ---------------------------------------------------------------------------
// launch
// ---------------------------------------------------------------------------
extern "C" void kernel_launch(void* const* d_in, const int* in_sizes, int n_in,
                              void* d_out, int out_size) {
    const int*   row  = (const int*)  d_in[0];
    const int*   col  = (const int*)  d_in[1];
    const float* vals = (const float*)d_in[2];
    const float* H    = (const float*)d_in[3];
    const float* W1   = (const float*)d_in[4];
    const float* b1   = (const float*)d_in[5];
    const float* W2   = (const float*)d_in[6];
    const float* b2   = (const float*)d_in[7];
    float* out = (float*)d_out;

    void *pAH_, *pH1_, *pAH1_, *pCnt_, *pRp_, *pLo_, *pCv_;
    cudaGetSymbolAddress(&pAH_,  g_AH);
    cudaGetSymbolAddress(&pH1_,  g_H1);
    cudaGetSymbolAddress(&pAH1_, g_AH1);
    cudaGetSymbolAddress(&pCnt_, g_counts);
    cudaGetSymbolAddress(&pRp_,  g_rowptr);
    cudaGetSymbolAddress(&pLo_,  g_localoff);
    cudaGetSymbolAddress(&pCv_,  g_csr_cv);
    float* pAH  = (float*)pAH_;
    float* pH1  = (float*)pH1_;
    float* pAH1 = (float*)pAH1_;
    int*   pCnt = (int*)pCnt_;
    int*   pRp  = (int*)pRp_;
    int*   pLo  = (int*)pLo_;
    int2*  pCv  = (int2*)pCv_;

    cudaFuncSetAttribute(gemm_bias_relu<64>,
                         cudaFuncAttributeMaxDynamicSharedMemorySize,
                         (64 * 128 + 64 * 64) * 4);
    cudaFuncSetAttribute(gemm_bias_relu<128>,
                         cudaFuncAttributeMaxDynamicSharedMemorySize,
                         (128 * 128 + 64 * 128) * 4);

    // ---- CSR build
    cudaMemsetAsync(pCnt, 0, N_NODES * sizeof(int));
    hist_off_kernel<<<(N_EDGES + 255) / 256, 256>>>(row, pCnt, pLo);
    scan_kernel<<<1, 1024>>>(pCnt, pRp);
    build_csr_kernel<<<(N_EDGES + 255) / 256, 256>>>(row, col, vals, pLo, pRp, pCv);

    const int warps_grid = (N_NODES * 32 + 255) / 256;   // 1 warp per row
    const int gblocks = (N_NODES + 63) / 64;

    // ---- layer 0
    spmm_gather64<<<warps_grid, 256>>>(pRp, pCv, H, pAH);
    gemm_bias_relu<64><<<gblocks, 256, (64 * 128 + 64 * 64) * 4>>>(pAH, W1, b1, pH1);

    // ---- layer 1
    spmm_gather128<<<warps_grid, 256>>>(pRp, pCv, pH1, pAH1);
    gemm_bias_relu<128><<<gblocks, 256, (128 * 128 + 64 * 128) * 4>>>(pAH1, W2, b2, out);
}

// round 4
// speedup vs baseline: 1.2055x; 1.0090x over previous
#include <cuda_runtime.h>
#include <cuda_bf16.h>
#include <cstdint>

#define N_NODES 100000
#define N_EDGES 1600000
#define D_FEAT  64
#define U1      128
#define U2      128

// ---------------------------------------------------------------------------
// Scratch (allocation-free rule: __device__ globals)
// ---------------------------------------------------------------------------
__device__ float g_AH [(size_t)N_NODES * D_FEAT];   // 25.6 MB
__device__ float g_H1 [(size_t)N_NODES * U1];       // 51.2 MB
__device__ float g_AH1[(size_t)N_NODES * U1];       // 51.2 MB
__device__ int   g_counts[N_NODES];
__device__ int   g_rowptr[N_NODES + 1];
__device__ int   g_localoff[N_EDGES];               // 6.4 MB
__device__ int4  g_csr_cv[N_EDGES / 2];             // packed (col,val) pairs, 12.8 MB

// ---------------------------------------------------------------------------
// CSR build
// ---------------------------------------------------------------------------
// pass 1: histogram + per-edge local offset (the ONLY atomic pass)
__global__ void hist_off_kernel(const int* __restrict__ row,
                                int* __restrict__ counts,
                                int* __restrict__ localoff) {
    int e = blockIdx.x * blockDim.x + threadIdx.x;
    if (e < N_EDGES) localoff[e] = atomicAdd(&counts[row[e]], 1);
}

// pass 2: single-block warp-shuffle exclusive scan -> rowptr
__global__ void scan_kernel(const int* __restrict__ counts,
                            int* __restrict__ rowptr) {
    const int tid  = threadIdx.x;
    const int lane = tid & 31;
    const int wid  = tid >> 5;
    const int CH   = (N_NODES + 1023) / 1024;        // 98
    int beg = tid * CH;
    int end = beg + CH; if (end > N_NODES) end = N_NODES;
    if (beg > N_NODES) beg = N_NODES;

    int s = 0;
    for (int i = beg; i < end; i++) s += counts[i];

    // warp inclusive scan
    int v = s;
    #pragma unroll
    for (int o = 1; o < 32; o <<= 1) {
        int t = __shfl_up_sync(0xFFFFFFFFu, v, o);
        if (lane >= o) v += t;
    }
    __shared__ int wsum[32];
    if (lane == 31) wsum[wid] = v;
    __syncthreads();
    if (wid == 0) {
        int x = wsum[lane];
        #pragma unroll
        for (int o = 1; o < 32; o <<= 1) {
            int t = __shfl_up_sync(0xFFFFFFFFu, x, o);
            if (lane >= o) x += t;
        }
        wsum[lane] = x;
    }
    __syncthreads();
    int incl = v + (wid > 0 ? wsum[wid - 1] : 0);
    int run  = incl - s;                              // exclusive prefix

    for (int i = beg; i < end; i++) {
        rowptr[i] = run;
        run += counts[i];
    }
    if (tid == 1023) rowptr[N_NODES] = run;           // == N_EDGES
}

// pass 3: atomic-free scatter of packed (col, val) payload into CSR order
__global__ void build_csr_kernel(const int* __restrict__ row,
                                 const int* __restrict__ col,
                                 const float* __restrict__ vals,
                                 const int* __restrict__ localoff,
                                 const int* __restrict__ rowptr,
                                 int2* __restrict__ cv) {
    int e = blockIdx.x * blockDim.x + threadIdx.x;
    if (e >= N_EDGES) return;
    int p = __ldg(rowptr + row[e]) + localoff[e];
    cv[p] = make_int2(col[e], __float_as_int(vals[e]));
}

// ---------------------------------------------------------------------------
// Gather SpMM: one warp per output row, no atomics, packed int2 payload,
// edge unroll 8 via aligned int4 loads (4 metadata LDG + 8 gathers / 8 edges).
// ---------------------------------------------------------------------------
__global__ void spmm_gather128(const int* __restrict__ rowptr,
                               const int2* __restrict__ cv,
                               const float* __restrict__ H,
                               float* __restrict__ out) {
    int warp = (blockIdx.x * blockDim.x + threadIdx.x) >> 5;
    int lane = threadIdx.x & 31;
    if (warp >= N_NODES) return;

    int beg = __ldg(rowptr + warp);
    int end = __ldg(rowptr + warp + 1);

    const float4* H4 = reinterpret_cast<const float4*>(H);
    float4 acc = make_float4(0.f, 0.f, 0.f, 0.f);

    int e = beg;
    // align e to even for int4 loads
    if ((e & 1) && e < end) {
        int2 p = __ldg(cv + e);
        float v = __int_as_float(p.y);
        float4 h = __ldg(H4 + (size_t)p.x * 32 + lane);
        acc.x = fmaf(v, h.x, acc.x); acc.y = fmaf(v, h.y, acc.y);
        acc.z = fmaf(v, h.z, acc.z); acc.w = fmaf(v, h.w, acc.w);
        e++;
    }
    const int4* CV4 = reinterpret_cast<const int4*>(cv);
    for (; e + 8 <= end; e += 8) {
        int4 q0 = __ldg(CV4 + (e >> 1) + 0);
        int4 q1 = __ldg(CV4 + (e >> 1) + 1);
        int4 q2 = __ldg(CV4 + (e >> 1) + 2);
        int4 q3 = __ldg(CV4 + (e >> 1) + 3);
        float4 h0 = __ldg(H4 + (size_t)q0.x * 32 + lane);
        float4 h1 = __ldg(H4 + (size_t)q0.z * 32 + lane);
        float4 h2 = __ldg(H4 + (size_t)q1.x * 32 + lane);
        float4 h3 = __ldg(H4 + (size_t)q1.z * 32 + lane);
        float4 h4 = __ldg(H4 + (size_t)q2.x * 32 + lane);
        float4 h5 = __ldg(H4 + (size_t)q2.z * 32 + lane);
        float4 h6 = __ldg(H4 + (size_t)q3.x * 32 + lane);
        float4 h7 = __ldg(H4 + (size_t)q3.z * 32 + lane);
        float v0 = __int_as_float(q0.y), v1 = __int_as_float(q0.w);
        float v2 = __int_as_float(q1.y), v3 = __int_as_float(q1.w);
        float v4 = __int_as_float(q2.y), v5 = __int_as_float(q2.w);
        float v6 = __int_as_float(q3.y), v7 = __int_as_float(q3.w);
        acc.x = fmaf(v0, h0.x, acc.x); acc.y = fmaf(v0, h0.y, acc.y);
        acc.z = fmaf(v0, h0.z, acc.z); acc.w = fmaf(v0, h0.w, acc.w);
        acc.x = fmaf(v1, h1.x, acc.x); acc.y = fmaf(v1, h1.y, acc.y);
        acc.z = fmaf(v1, h1.z, acc.z); acc.w = fmaf(v1, h1.w, acc.w);
        acc.x = fmaf(v2, h2.x, acc.x); acc.y = fmaf(v2, h2.y, acc.y);
        acc.z = fmaf(v2, h2.z, acc.z); acc.w = fmaf(v2, h2.w, acc.w);
        acc.x = fmaf(v3, h3.x, acc.x); acc.y = fmaf(v3, h3.y, acc.y);
        acc.z = fmaf(v3, h3.z, acc.z); acc.w = fmaf(v3, h3.w, acc.w);
        acc.x = fmaf(v4, h4.x, acc.x); acc.y = fmaf(v4, h4.y, acc.y);
        acc.z = fmaf(v4, h4.z, acc.z); acc.w = fmaf(v4, h4.w, acc.w);
        acc.x = fmaf(v5, h5.x, acc.x); acc.y = fmaf(v5, h5.y, acc.y);
        acc.z = fmaf(v5, h5.z, acc.z); acc.w = fmaf(v5, h5.w, acc.w);
        acc.x = fmaf(v6, h6.x, acc.x); acc.y = fmaf(v6, h6.y, acc.y);
        acc.z = fmaf(v6, h6.z, acc.z); acc.w = fmaf(v6, h6.w, acc.w);
        acc.x = fmaf(v7, h7.x, acc.x); acc.y = fmaf(v7, h7.y, acc.y);
        acc.z = fmaf(v7, h7.z, acc.z); acc.w = fmaf(v7, h7.w, acc.w);
    }
    for (; e + 2 <= end; e += 2) {
        int4 q = __ldg(CV4 + (e >> 1));
        float4 h0 = __ldg(H4 + (size_t)q.x * 32 + lane);
        float4 h1 = __ldg(H4 + (size_t)q.z * 32 + lane);
        float v0 = __int_as_float(q.y), v1 = __int_as_float(q.w);
        acc.x = fmaf(v0, h0.x, acc.x); acc.y = fmaf(v0, h0.y, acc.y);
        acc.z = fmaf(v0, h0.z, acc.z); acc.w = fmaf(v0, h0.w, acc.w);
        acc.x = fmaf(v1, h1.x, acc.x); acc.y = fmaf(v1, h1.y, acc.y);
        acc.z = fmaf(v1, h1.z, acc.z); acc.w = fmaf(v1, h1.w, acc.w);
    }
    if (e < end) {
        int2 p = __ldg(cv + e);
        float v = __int_as_float(p.y);
        float4 h = __ldg(H4 + (size_t)p.x * 32 + lane);
        acc.x = fmaf(v, h.x, acc.x); acc.y = fmaf(v, h.y, acc.y);
        acc.z = fmaf(v, h.z, acc.z); acc.w = fmaf(v, h.w, acc.w);
    }
    reinterpret_cast<float4*>(out)[(size_t)warp * 32 + lane] = acc;
}

__global__ void spmm_gather64(const int* __restrict__ rowptr,
                              const int2* __restrict__ cv,
                              const float* __restrict__ H,
                              float* __restrict__ out) {
    int warp = (blockIdx.x * blockDim.x + threadIdx.x) >> 5;
    int lane = threadIdx.x & 31;
    if (warp >= N_NODES) return;

    int beg = __ldg(rowptr + warp);
    int end = __ldg(rowptr + warp + 1);

    const float2* H2 = reinterpret_cast<const float2*>(H);
    float2 acc = make_float2(0.f, 0.f);

    int e = beg;
    if ((e & 1) && e < end) {
        int2 p = __ldg(cv + e);
        float v = __int_as_float(p.y);
        float2 h = __ldg(H2 + (size_t)p.x * 32 + lane);
        acc.x = fmaf(v, h.x, acc.x); acc.y = fmaf(v, h.y, acc.y);
        e++;
    }
    const int4* CV4 = reinterpret_cast<const int4*>(cv);
    for (; e + 8 <= end; e += 8) {
        int4 q0 = __ldg(CV4 + (e >> 1) + 0);
        int4 q1 = __ldg(CV4 + (e >> 1) + 1);
        int4 q2 = __ldg(CV4 + (e >> 1) + 2);
        int4 q3 = __ldg(CV4 + (e >> 1) + 3);
        float2 h0 = __ldg(H2 + (size_t)q0.x * 32 + lane);
        float2 h1 = __ldg(H2 + (size_t)q0.z * 32 + lane);
        float2 h2 = __ldg(H2 + (size_t)q1.x * 32 + lane);
        float2 h3 = __ldg(H2 + (size_t)q1.z * 32 + lane);
        float2 h4 = __ldg(H2 + (size_t)q2.x * 32 + lane);
        float2 h5 = __ldg(H2 + (size_t)q2.z * 32 + lane);
        float2 h6 = __ldg(H2 + (size_t)q3.x * 32 + lane);
        float2 h7 = __ldg(H2 + (size_t)q3.z * 32 + lane);
        float v0 = __int_as_float(q0.y), v1 = __int_as_float(q0.w);
        float v2 = __int_as_float(q1.y), v3 = __int_as_float(q1.w);
        float v4 = __int_as_float(q2.y), v5 = __int_as_float(q2.w);
        float v6 = __int_as_float(q3.y), v7 = __int_as_float(q3.w);
        acc.x = fmaf(v0, h0.x, acc.x); acc.y = fmaf(v0, h0.y, acc.y);
        acc.x = fmaf(v1, h1.x, acc.x); acc.y = fmaf(v1, h1.y, acc.y);
        acc.x = fmaf(v2, h2.x, acc.x); acc.y = fmaf(v2, h2.y, acc.y);
        acc.x = fmaf(v3, h3.x, acc.x); acc.y = fmaf(v3, h3.y, acc.y);
        acc.x = fmaf(v4, h4.x, acc.x); acc.y = fmaf(v4, h4.y, acc.y);
        acc.x = fmaf(v5, h5.x, acc.x); acc.y = fmaf(v5, h5.y, acc.y);
        acc.x = fmaf(v6, h6.x, acc.x); acc.y = fmaf(v6, h6.y, acc.y);
        acc.x = fmaf(v7, h7.x, acc.x); acc.y = fmaf(v7, h7.y, acc.y);
    }
    for (; e + 2 <= end; e += 2) {
        int4 q = __ldg(CV4 + (e >> 1));
        float2 h0 = __ldg(H2 + (size_t)q.x * 32 + lane);
        float2 h1 = __ldg(H2 + (size_t)q.z * 32 + lane);
        float v0 = __int_as_float(q.y), v1 = __int_as_float(q.w);
        acc.x = fmaf(v0, h0.x, acc.x); acc.y = fmaf(v0, h0.y, acc.y);
        acc.x = fmaf(v1, h1.x, acc.x); acc.y = fmaf(v1, h1.y, acc.y);
    }
    if (e < end) {
        int2 p = __ldg(cv + e);
        float v = __int_as_float(p.y);
        float2 h = __ldg(H2 + (size_t)p.x * 32 + lane);
        acc.x = fmaf(v, h.x, acc.x); acc.y = fmaf(v, h.y, acc.y);
    }
    reinterpret_cast<float2*>(out)[(size_t)warp * 32 + lane] = acc;
}

// ---------------------------------------------------------------------------
// GEMM + bias + ReLU:  out[N,128] = relu(A[N,K] @ W[K,128] + b)
// 64-row x 128-col block tile; thread = 8 rows x 4 cols; k unrolled x4 with
// float4 A loads: 12 LDS.128 per 128 FFMA.
// ---------------------------------------------------------------------------
template <int K>
__global__ void gemm_bias_relu(const float* __restrict__ A,
                               const float* __restrict__ W,
                               const float* __restrict__ b,
                               float* __restrict__ out) {
    extern __shared__ float smem[];
    float* Ws = smem;             // K*128 floats
    float* As = smem + K * 128;   // 64*K  floats

    int tid = threadIdx.x;

    const float4* W4 = reinterpret_cast<const float4*>(W);
    float4* Ws4v = reinterpret_cast<float4*>(Ws);
    #pragma unroll
    for (int i = tid; i < K * 32; i += 256) Ws4v[i] = W4[i];

    int row0 = blockIdx.x * 64;
    const float4* A4 = reinterpret_cast<const float4*>(A);
    float4* As4 = reinterpret_cast<float4*>(As);
    constexpr int K4 = K / 4;
    #pragma unroll
    for (int i = tid; i < 64 * K4; i += 256) {
        int r = row0 + i / K4;
        As4[i] = (r < N_NODES) ? __ldg(A4 + (size_t)r * K4 + (i % K4))
                               : make_float4(0.f, 0.f, 0.f, 0.f);
    }
    __syncthreads();

    int cx = tid & 31;
    int ry = tid >> 5;

    float4 bias = reinterpret_cast<const float4*>(b)[cx];
    float4 acc[8];
    #pragma unroll
    for (int i = 0; i < 8; i++) acc[i] = bias;

    const float4* Ws4 = reinterpret_cast<const float4*>(Ws);
    const float4* Atile = reinterpret_cast<const float4*>(As) + (ry * 8) * K4;

    #pragma unroll
    for (int k = 0; k < K; k += 4) {
        float4 w0 = Ws4[(k + 0) * 32 + cx];
        float4 w1 = Ws4[(k + 1) * 32 + cx];
        float4 w2 = Ws4[(k + 2) * 32 + cx];
        float4 w3 = Ws4[(k + 3) * 32 + cx];
        #pragma unroll
        for (int i = 0; i < 8; i++) {
            float4 a = Atile[i * K4 + (k >> 2)];
            acc[i].x = fmaf(a.x, w0.x, acc[i].x);
            acc[i].y = fmaf(a.x, w0.y, acc[i].y);
            acc[i].z = fmaf(a.x, w0.z, acc[i].z);
            acc[i].w = fmaf(a.x, w0.w, acc[i].w);
            acc[i].x = fmaf(a.y, w1.x, acc[i].x);
            acc[i].y = fmaf(a.y, w1.y, acc[i].y);
            acc[i].z = fmaf(a.y, w1.z, acc[i].z);
            acc[i].w = fmaf(a.y, w1.w, acc[i].w);
            acc[i].x = fmaf(a.z, w2.x, acc[i].x);
            acc[i].y = fmaf(a.z, w2.y, acc[i].y);
            acc[i].z = fmaf(a.z, w2.z, acc[i].z);
            acc[i].w = fmaf(a.z, w2.w, acc[i].w);
            acc[i].x = fmaf(a.w, w3.x, acc[i].x);
            acc[i].y = fmaf(a.w, w3.y, acc[i].y);
            acc[i].z = fmaf(a.w, w3.z, acc[i].z);
            acc[i].w = fmaf(a.w, w3.w, acc[i].w);
        }
    }

    #pragma unroll
    for (int i = 0; i < 8; i++) {
        int r = row0 + ry * 8 + i;
        if (r < N_NODES) {
            float4 o = make_float4(fmaxf(acc[i].x, 0.f), fmaxf(acc[i].y, 0.f),
                                   fmaxf(acc[i].z, 0.f), fmaxf(acc[i].w, 0.f));
            reinterpret_cast<float4*>(out + (size_t)r * 128)[cx] = o;
        }
    }
}

// ---------------------------------------------------------------------------
// launch
// ---------------------------------------------------------------------------
extern "C" void kernel_launch(void* const* d_in, const int* in_sizes, int n_in,
                              void* d_out, int out_size) {
    const int*   row  = (const int*)  d_in[0];
    const int*   col  = (const int*)  d_in[1];
    const float* vals = (const float*)d_in[2];
    const float* H    = (const float*)d_in[3];
    const float* W1   = (const float*)d_in[4];
    const float* b1   = (const float*)d_in[5];
    const float* W2   = (const float*)d_in[6];
    const float* b2   = (const float*)d_in[7];
    float* out = (float*)d_out;

    void *pAH_, *pH1_, *pAH1_, *pCnt_, *pRp_, *pLo_, *pCv_;
    cudaGetSymbolAddress(&pAH_,  g_AH);
    cudaGetSymbolAddress(&pH1_,  g_H1);
    cudaGetSymbolAddress(&pAH1_, g_AH1);
    cudaGetSymbolAddress(&pCnt_, g_counts);
    cudaGetSymbolAddress(&pRp_,  g_rowptr);
    cudaGetSymbolAddress(&pLo_,  g_localoff);
    cudaGetSymbolAddress(&pCv_,  g_csr_cv);
    float* pAH  = (float*)pAH_;
    float* pH1  = (float*)pH1_;
    float* pAH1 = (float*)pAH1_;
    int*   pCnt = (int*)pCnt_;
    int*   pRp  = (int*)pRp_;
    int*   pLo  = (int*)pLo_;
    int2*  pCv  = (int2*)pCv_;

    cudaFuncSetAttribute(gemm_bias_relu<64>,
                         cudaFuncAttributeMaxDynamicSharedMemorySize,
                         (64 * 128 + 64 * 64) * 4);
    cudaFuncSetAttribute(gemm_bias_relu<128>,
                         cudaFuncAttributeMaxDynamicSharedMemorySize,
                         (128 * 128 + 64 * 128) * 4);

    // ---- CSR build
    cudaMemsetAsync(pCnt, 0, N_NODES * sizeof(int));
    hist_off_kernel<<<(N_EDGES + 255) / 256, 256>>>(row, pCnt, pLo);
    scan_kernel<<<1, 1024>>>(pCnt, pRp);
    build_csr_kernel<<<(N_EDGES + 255) / 256, 256>>>(row, col, vals, pLo, pRp, pCv);

    const int warps_grid = (N_NODES * 32 + 255) / 256;   // 1 warp per row
    const int gblocks = (N_NODES + 63) / 64;

    // ---- layer 0
    spmm_gather64<<<warps_grid, 256>>>(pRp, pCv, H, pAH);
    gemm_bias_relu<64><<<gblocks, 256, (64 * 128 + 64 * 64) * 4>>>(pAH, W1, b1, pH1);

    // ---- layer 1
    spmm_gather128<<<warps_grid, 256>>>(pRp, pCv, pH1, pAH1);
    gemm_bias_relu<128><<<gblocks, 256, (128 * 128 + 64 * 128) * 4>>>(pAH1, W2, b2, out);
}

// round 5
// speedup vs baseline: 1.2722x; 1.0553x over previous
#include <cuda_runtime.h>
#include <cuda_bf16.h>
#include <cuda_fp16.h>
#include <cstdint>

#define N_NODES 100000
#define N_EDGES 1600000
#define D_FEAT  64
#define U1      128
#define U2      128

// ---------------------------------------------------------------------------
// Scratch (allocation-free rule: __device__ globals)
// ---------------------------------------------------------------------------
__device__ float  g_AH [(size_t)N_NODES * D_FEAT];   // 25.6 MB
__device__ __half g_H1h[(size_t)N_NODES * U1];       // 25.6 MB (fp16 features)
__device__ float  g_AH1[(size_t)N_NODES * U1];       // 51.2 MB
__device__ int    g_counts[N_NODES];
__device__ int    g_rowptr[N_NODES + 1];
__device__ int    g_localoff[N_EDGES];               // 6.4 MB
__device__ int4   g_csr_cv[N_EDGES / 2];             // packed (col,val), 12.8 MB

// ---------------------------------------------------------------------------
// CSR build
// ---------------------------------------------------------------------------
__global__ void hist_off_kernel(const int* __restrict__ row,
                                int* __restrict__ counts,
                                int* __restrict__ localoff) {
    int e = blockIdx.x * blockDim.x + threadIdx.x;
    if (e < N_EDGES) localoff[e] = atomicAdd(&counts[row[e]], 1);
}

__global__ void scan_kernel(const int* __restrict__ counts,
                            int* __restrict__ rowptr) {
    const int tid  = threadIdx.x;
    const int lane = tid & 31;
    const int wid  = tid >> 5;
    const int CH   = (N_NODES + 1023) / 1024;        // 98
    int beg = tid * CH;
    int end = beg + CH; if (end > N_NODES) end = N_NODES;
    if (beg > N_NODES) beg = N_NODES;

    int s = 0;
    for (int i = beg; i < end; i++) s += counts[i];

    int v = s;
    #pragma unroll
    for (int o = 1; o < 32; o <<= 1) {
        int t = __shfl_up_sync(0xFFFFFFFFu, v, o);
        if (lane >= o) v += t;
    }
    __shared__ int wsum[32];
    if (lane == 31) wsum[wid] = v;
    __syncthreads();
    if (wid == 0) {
        int x = wsum[lane];
        #pragma unroll
        for (int o = 1; o < 32; o <<= 1) {
            int t = __shfl_up_sync(0xFFFFFFFFu, x, o);
            if (lane >= o) x += t;
        }
        wsum[lane] = x;
    }
    __syncthreads();
    int incl = v + (wid > 0 ? wsum[wid - 1] : 0);
    int run  = incl - s;

    for (int i = beg; i < end; i++) {
        rowptr[i] = run;
        run += counts[i];
    }
    if (tid == 1023) rowptr[N_NODES] = run;
}

__global__ void build_csr_kernel(const int* __restrict__ row,
                                 const int* __restrict__ col,
                                 const float* __restrict__ vals,
                                 const int* __restrict__ localoff,
                                 const int* __restrict__ rowptr,
                                 int2* __restrict__ cv) {
    int e = blockIdx.x * blockDim.x + threadIdx.x;
    if (e >= N_EDGES) return;
    int p = __ldg(rowptr + row[e]) + localoff[e];
    cv[p] = make_int2(col[e], __float_as_int(vals[e]));
}

// ---------------------------------------------------------------------------
// Gather SpMM (fp32 features, FEAT=64): one warp per row, float2 per lane.
// ---------------------------------------------------------------------------
__global__ void spmm_gather64(const int* __restrict__ rowptr,
                              const int2* __restrict__ cv,
                              const float* __restrict__ H,
                              float* __restrict__ out) {
    int warp = (blockIdx.x * blockDim.x + threadIdx.x) >> 5;
    int lane = threadIdx.x & 31;
    if (warp >= N_NODES) return;

    int beg = __ldg(rowptr + warp);
    int end = __ldg(rowptr + warp + 1);

    const float2* H2 = reinterpret_cast<const float2*>(H);
    float2 acc = make_float2(0.f, 0.f);

    int e = beg;
    if ((e & 1) && e < end) {
        int2 p = __ldg(cv + e);
        float v = __int_as_float(p.y);
        float2 h = __ldg(H2 + (size_t)p.x * 32 + lane);
        acc.x = fmaf(v, h.x, acc.x); acc.y = fmaf(v, h.y, acc.y);
        e++;
    }
    const int4* CV4 = reinterpret_cast<const int4*>(cv);
    for (; e + 8 <= end; e += 8) {
        int4 q0 = __ldg(CV4 + (e >> 1) + 0);
        int4 q1 = __ldg(CV4 + (e >> 1) + 1);
        int4 q2 = __ldg(CV4 + (e >> 1) + 2);
        int4 q3 = __ldg(CV4 + (e >> 1) + 3);
        float2 h0 = __ldg(H2 + (size_t)q0.x * 32 + lane);
        float2 h1 = __ldg(H2 + (size_t)q0.z * 32 + lane);
        float2 h2 = __ldg(H2 + (size_t)q1.x * 32 + lane);
        float2 h3 = __ldg(H2 + (size_t)q1.z * 32 + lane);
        float2 h4 = __ldg(H2 + (size_t)q2.x * 32 + lane);
        float2 h5 = __ldg(H2 + (size_t)q2.z * 32 + lane);
        float2 h6 = __ldg(H2 + (size_t)q3.x * 32 + lane);
        float2 h7 = __ldg(H2 + (size_t)q3.z * 32 + lane);
        float v0 = __int_as_float(q0.y), v1 = __int_as_float(q0.w);
        float v2 = __int_as_float(q1.y), v3 = __int_as_float(q1.w);
        float v4 = __int_as_float(q2.y), v5 = __int_as_float(q2.w);
        float v6 = __int_as_float(q3.y), v7 = __int_as_float(q3.w);
        acc.x = fmaf(v0, h0.x, acc.x); acc.y = fmaf(v0, h0.y, acc.y);
        acc.x = fmaf(v1, h1.x, acc.x); acc.y = fmaf(v1, h1.y, acc.y);
        acc.x = fmaf(v2, h2.x, acc.x); acc.y = fmaf(v2, h2.y, acc.y);
        acc.x = fmaf(v3, h3.x, acc.x); acc.y = fmaf(v3, h3.y, acc.y);
        acc.x = fmaf(v4, h4.x, acc.x); acc.y = fmaf(v4, h4.y, acc.y);
        acc.x = fmaf(v5, h5.x, acc.x); acc.y = fmaf(v5, h5.y, acc.y);
        acc.x = fmaf(v6, h6.x, acc.x); acc.y = fmaf(v6, h6.y, acc.y);
        acc.x = fmaf(v7, h7.x, acc.x); acc.y = fmaf(v7, h7.y, acc.y);
    }
    for (; e + 2 <= end; e += 2) {
        int4 q = __ldg(CV4 + (e >> 1));
        float2 h0 = __ldg(H2 + (size_t)q.x * 32 + lane);
        float2 h1 = __ldg(H2 + (size_t)q.z * 32 + lane);
        float v0 = __int_as_float(q.y), v1 = __int_as_float(q.w);
        acc.x = fmaf(v0, h0.x, acc.x); acc.y = fmaf(v0, h0.y, acc.y);
        acc.x = fmaf(v1, h1.x, acc.x); acc.y = fmaf(v1, h1.y, acc.y);
    }
    if (e < end) {
        int2 p = __ldg(cv + e);
        float v = __int_as_float(p.y);
        float2 h = __ldg(H2 + (size_t)p.x * 32 + lane);
        acc.x = fmaf(v, h.x, acc.x); acc.y = fmaf(v, h.y, acc.y);
    }
    reinterpret_cast<float2*>(out)[(size_t)warp * 32 + lane] = acc;
}

// ---------------------------------------------------------------------------
// Gather SpMM (fp16 features, FEAT=128): one warp per row.
// Lane gathers uint2 = 4 halfs (256 B/edge/warp), accumulates fp32.
// ---------------------------------------------------------------------------
__device__ __forceinline__ void fma_h4(float4& acc, float v, uint2 q) {
    __half2 a = *reinterpret_cast<__half2*>(&q.x);
    __half2 b = *reinterpret_cast<__half2*>(&q.y);
    float2 fa = __half22float2(a);
    float2 fb = __half22float2(b);
    acc.x = fmaf(v, fa.x, acc.x); acc.y = fmaf(v, fa.y, acc.y);
    acc.z = fmaf(v, fb.x, acc.z); acc.w = fmaf(v, fb.y, acc.w);
}

__global__ void spmm_gather128_h(const int* __restrict__ rowptr,
                                 const int2* __restrict__ cv,
                                 const __half* __restrict__ H,
                                 float* __restrict__ out) {
    int warp = (blockIdx.x * blockDim.x + threadIdx.x) >> 5;
    int lane = threadIdx.x & 31;
    if (warp >= N_NODES) return;

    int beg = __ldg(rowptr + warp);
    int end = __ldg(rowptr + warp + 1);

    const uint2* Hq = reinterpret_cast<const uint2*>(H);
    float4 acc = make_float4(0.f, 0.f, 0.f, 0.f);

    int e = beg;
    if ((e & 1) && e < end) {
        int2 p = __ldg(cv + e);
        float v = __int_as_float(p.y);
        uint2 h = __ldg(Hq + (size_t)p.x * 32 + lane);
        fma_h4(acc, v, h);
        e++;
    }
    const int4* CV4 = reinterpret_cast<const int4*>(cv);
    for (; e + 8 <= end; e += 8) {
        int4 q0 = __ldg(CV4 + (e >> 1) + 0);
        int4 q1 = __ldg(CV4 + (e >> 1) + 1);
        int4 q2 = __ldg(CV4 + (e >> 1) + 2);
        int4 q3 = __ldg(CV4 + (e >> 1) + 3);
        uint2 h0 = __ldg(Hq + (size_t)q0.x * 32 + lane);
        uint2 h1 = __ldg(Hq + (size_t)q0.z * 32 + lane);
        uint2 h2 = __ldg(Hq + (size_t)q1.x * 32 + lane);
        uint2 h3 = __ldg(Hq + (size_t)q1.z * 32 + lane);
        uint2 h4 = __ldg(Hq + (size_t)q2.x * 32 + lane);
        uint2 h5 = __ldg(Hq + (size_t)q2.z * 32 + lane);
        uint2 h6 = __ldg(Hq + (size_t)q3.x * 32 + lane);
        uint2 h7 = __ldg(Hq + (size_t)q3.z * 32 + lane);
        fma_h4(acc, __int_as_float(q0.y), h0);
        fma_h4(acc, __int_as_float(q0.w), h1);
        fma_h4(acc, __int_as_float(q1.y), h2);
        fma_h4(acc, __int_as_float(q1.w), h3);
        fma_h4(acc, __int_as_float(q2.y), h4);
        fma_h4(acc, __int_as_float(q2.w), h5);
        fma_h4(acc, __int_as_float(q3.y), h6);
        fma_h4(acc, __int_as_float(q3.w), h7);
    }
    for (; e + 2 <= end; e += 2) {
        int4 q = __ldg(CV4 + (e >> 1));
        uint2 h0 = __ldg(Hq + (size_t)q.x * 32 + lane);
        uint2 h1 = __ldg(Hq + (size_t)q.z * 32 + lane);
        fma_h4(acc, __int_as_float(q.y), h0);
        fma_h4(acc, __int_as_float(q.w), h1);
    }
    if (e < end) {
        int2 p = __ldg(cv + e);
        uint2 h = __ldg(Hq + (size_t)p.x * 32 + lane);
        fma_h4(acc, __int_as_float(p.y), h);
    }
    reinterpret_cast<float4*>(out)[(size_t)warp * 32 + lane] = acc;
}

// ---------------------------------------------------------------------------
// GEMM + bias + ReLU:  out[N,128] = relu(A[N,K] @ W[K,128] + b)
// 64-row x 128-col tile; thread = 8 rows x 4 cols; k unrolled x4.
// HALF_OUT: write fp16 (feeds the fp16 gather).
// ---------------------------------------------------------------------------
template <int K, bool HALF_OUT>
__global__ void gemm_bias_relu(const float* __restrict__ A,
                               const float* __restrict__ W,
                               const float* __restrict__ b,
                               void* __restrict__ out_) {
    extern __shared__ float smem[];
    float* Ws = smem;             // K*128 floats
    float* As = smem + K * 128;   // 64*K  floats

    int tid = threadIdx.x;

    const float4* W4 = reinterpret_cast<const float4*>(W);
    float4* Ws4v = reinterpret_cast<float4*>(Ws);
    #pragma unroll
    for (int i = tid; i < K * 32; i += 256) Ws4v[i] = W4[i];

    int row0 = blockIdx.x * 64;
    const float4* A4 = reinterpret_cast<const float4*>(A);
    float4* As4 = reinterpret_cast<float4*>(As);
    constexpr int K4 = K / 4;
    #pragma unroll
    for (int i = tid; i < 64 * K4; i += 256) {
        int r = row0 + i / K4;
        As4[i] = (r < N_NODES) ? __ldg(A4 + (size_t)r * K4 + (i % K4))
                               : make_float4(0.f, 0.f, 0.f, 0.f);
    }
    __syncthreads();

    int cx = tid & 31;
    int ry = tid >> 5;

    float4 bias = reinterpret_cast<const float4*>(b)[cx];
    float4 acc[8];
    #pragma unroll
    for (int i = 0; i < 8; i++) acc[i] = bias;

    const float4* Ws4 = reinterpret_cast<const float4*>(Ws);
    const float4* Atile = reinterpret_cast<const float4*>(As) + (ry * 8) * K4;

    #pragma unroll
    for (int k = 0; k < K; k += 4) {
        float4 w0 = Ws4[(k + 0) * 32 + cx];
        float4 w1 = Ws4[(k + 1) * 32 + cx];
        float4 w2 = Ws4[(k + 2) * 32 + cx];
        float4 w3 = Ws4[(k + 3) * 32 + cx];
        #pragma unroll
        for (int i = 0; i < 8; i++) {
            float4 a = Atile[i * K4 + (k >> 2)];
            acc[i].x = fmaf(a.x, w0.x, acc[i].x);
            acc[i].y = fmaf(a.x, w0.y, acc[i].y);
            acc[i].z = fmaf(a.x, w0.z, acc[i].z);
            acc[i].w = fmaf(a.x, w0.w, acc[i].w);
            acc[i].x = fmaf(a.y, w1.x, acc[i].x);
            acc[i].y = fmaf(a.y, w1.y, acc[i].y);
            acc[i].z = fmaf(a.y, w1.z, acc[i].z);
            acc[i].w = fmaf(a.y, w1.w, acc[i].w);
            acc[i].x = fmaf(a.z, w2.x, acc[i].x);
            acc[i].y = fmaf(a.z, w2.y, acc[i].y);
            acc[i].z = fmaf(a.z, w2.z, acc[i].z);
            acc[i].w = fmaf(a.z, w2.w, acc[i].w);
            acc[i].x = fmaf(a.w, w3.x, acc[i].x);
            acc[i].y = fmaf(a.w, w3.y, acc[i].y);
            acc[i].z = fmaf(a.w, w3.z, acc[i].z);
            acc[i].w = fmaf(a.w, w3.w, acc[i].w);
        }
    }

    #pragma unroll
    for (int i = 0; i < 8; i++) {
        int r = row0 + ry * 8 + i;
        if (r < N_NODES) {
            float4 o = make_float4(fmaxf(acc[i].x, 0.f), fmaxf(acc[i].y, 0.f),
                                   fmaxf(acc[i].z, 0.f), fmaxf(acc[i].w, 0.f));
            if (HALF_OUT) {
                __half2 lo = __floats2half2_rn(o.x, o.y);
                __half2 hi = __floats2half2_rn(o.z, o.w);
                uint2 st;
                st.x = *reinterpret_cast<unsigned*>(&lo);
                st.y = *reinterpret_cast<unsigned*>(&hi);
                reinterpret_cast<uint2*>((__half*)out_ + (size_t)r * 128)[cx] = st;
            } else {
                reinterpret_cast<float4*>((float*)out_ + (size_t)r * 128)[cx] = o;
            }
        }
    }
}

// ---------------------------------------------------------------------------
// launch
// ---------------------------------------------------------------------------
extern "C" void kernel_launch(void* const* d_in, const int* in_sizes, int n_in,
                              void* d_out, int out_size) {
    const int*   row  = (const int*)  d_in[0];
    const int*   col  = (const int*)  d_in[1];
    const float* vals = (const float*)d_in[2];
    const float* H    = (const float*)d_in[3];
    const float* W1   = (const float*)d_in[4];
    const float* b1   = (const float*)d_in[5];
    const float* W2   = (const float*)d_in[6];
    const float* b2   = (const float*)d_in[7];
    float* out = (float*)d_out;

    void *pAH_, *pH1_, *pAH1_, *pCnt_, *pRp_, *pLo_, *pCv_;
    cudaGetSymbolAddress(&pAH_,  g_AH);
    cudaGetSymbolAddress(&pH1_,  g_H1h);
    cudaGetSymbolAddress(&pAH1_, g_AH1);
    cudaGetSymbolAddress(&pCnt_, g_counts);
    cudaGetSymbolAddress(&pRp_,  g_rowptr);
    cudaGetSymbolAddress(&pLo_,  g_localoff);
    cudaGetSymbolAddress(&pCv_,  g_csr_cv);
    float*  pAH  = (float*)pAH_;
    __half* pH1  = (__half*)pH1_;
    float*  pAH1 = (float*)pAH1_;
    int*    pCnt = (int*)pCnt_;
    int*    pRp  = (int*)pRp_;
    int*    pLo  = (int*)pLo_;
    int2*   pCv  = (int2*)pCv_;

    cudaFuncSetAttribute(gemm_bias_relu<64, true>,
                         cudaFuncAttributeMaxDynamicSharedMemorySize,
                         (64 * 128 + 64 * 64) * 4);
    cudaFuncSetAttribute(gemm_bias_relu<128, false>,
                         cudaFuncAttributeMaxDynamicSharedMemorySize,
                         (128 * 128 + 64 * 128) * 4);

    // ---- CSR build
    cudaMemsetAsync(pCnt, 0, N_NODES * sizeof(int));
    hist_off_kernel<<<(N_EDGES + 255) / 256, 256>>>(row, pCnt, pLo);
    scan_kernel<<<1, 1024>>>(pCnt, pRp);
    build_csr_kernel<<<(N_EDGES + 255) / 256, 256>>>(row, col, vals, pLo, pRp, pCv);

    const int warps_grid = (N_NODES * 32 + 255) / 256;   // 1 warp per row
    const int gblocks = (N_NODES + 63) / 64;

    // ---- layer 0: AH = A@H (fp32); H1 = relu(AH@W1+b1) stored fp16
    spmm_gather64<<<warps_grid, 256>>>(pRp, pCv, H, pAH);
    gemm_bias_relu<64, true><<<gblocks, 256, (64 * 128 + 64 * 64) * 4>>>(
        pAH, W1, b1, pH1);

    // ---- layer 1: AH1 = A@H1 (fp16 gather, fp32 accum); out = relu(AH1@W2+b2)
    spmm_gather128_h<<<warps_grid, 256>>>(pRp, pCv, pH1, pAH1);
    gemm_bias_relu<128, false><<<gblocks, 256, (128 * 128 + 64 * 128) * 4>>>(
        pAH1, W2, b2, out);
}

// round 6
// speedup vs baseline: 1.6490x; 1.2962x over previous
#include <cuda_runtime.h>
#include <cuda_bf16.h>
#include <cuda_fp16.h>
#include <cstdint>

#define N_NODES 100000
#define N_EDGES 1600000
#define D_FEAT  64
#define U1      128
#define U2      128

// ---------------------------------------------------------------------------
// Scratch (allocation-free rule: __device__ globals)
// ---------------------------------------------------------------------------
__device__ __half g_Hh  [(size_t)N_NODES * D_FEAT];  // 12.8 MB  fp16 input feats
__device__ __half g_AHh [(size_t)N_NODES * D_FEAT];  // 12.8 MB  fp16 A@H
__device__ __half g_H1h [(size_t)N_NODES * U1];      // 25.6 MB  fp16 layer-1 feats
__device__ __half g_AH1h[(size_t)N_NODES * U1];      // 25.6 MB  fp16 A@H1
__device__ __half g_W1t [U1 * D_FEAT];               // W1^T  [n][k] fp16
__device__ __half g_W2t [U2 * U1];                   // W2^T  [n][k] fp16
__device__ int    g_counts[N_NODES];
__device__ int    g_rowptr[N_NODES + 1];
__device__ int    g_localoff[N_EDGES];
__device__ int4   g_csr_cv[N_EDGES / 2];             // packed (col,val) 12.8 MB

// ---------------------------------------------------------------------------
// prep: H fp32 -> fp16 ; W transpose+convert
// ---------------------------------------------------------------------------
__global__ void prep_h_kernel(const float* __restrict__ H, __half* __restrict__ Hh) {
    int i = blockIdx.x * blockDim.x + threadIdx.x;          // over N*64/2
    if (i < N_NODES * D_FEAT / 2) {
        float2 f = reinterpret_cast<const float2*>(H)[i];
        reinterpret_cast<__half2*>(Hh)[i] = __floats2half2_rn(f.x, f.y);
    }
}

template <int K, int N>
__global__ void prep_wt_kernel(const float* __restrict__ W, __half* __restrict__ Wt) {
    int i = blockIdx.x * blockDim.x + threadIdx.x;          // over K*N
    if (i < K * N) {
        int k = i / N, n = i % N;
        Wt[n * K + k] = __float2half(W[i]);
    }
}

// ---------------------------------------------------------------------------
// CSR build
// ---------------------------------------------------------------------------
__global__ void hist_off_kernel(const int* __restrict__ row,
                                int* __restrict__ counts,
                                int* __restrict__ localoff) {
    int e = blockIdx.x * blockDim.x + threadIdx.x;
    if (e < N_EDGES) localoff[e] = atomicAdd(&counts[row[e]], 1);
}

__global__ void scan_kernel(const int* __restrict__ counts,
                            int* __restrict__ rowptr) {
    const int tid  = threadIdx.x;
    const int lane = tid & 31;
    const int wid  = tid >> 5;
    const int CH   = (N_NODES + 1023) / 1024;
    int beg = tid * CH;
    int end = beg + CH; if (end > N_NODES) end = N_NODES;
    if (beg > N_NODES) beg = N_NODES;

    int s = 0;
    for (int i = beg; i < end; i++) s += counts[i];

    int v = s;
    #pragma unroll
    for (int o = 1; o < 32; o <<= 1) {
        int t = __shfl_up_sync(0xFFFFFFFFu, v, o);
        if (lane >= o) v += t;
    }
    __shared__ int wsum[32];
    if (lane == 31) wsum[wid] = v;
    __syncthreads();
    if (wid == 0) {
        int x = wsum[lane];
        #pragma unroll
        for (int o = 1; o < 32; o <<= 1) {
            int t = __shfl_up_sync(0xFFFFFFFFu, x, o);
            if (lane >= o) x += t;
        }
        wsum[lane] = x;
    }
    __syncthreads();
    int incl = v + (wid > 0 ? wsum[wid - 1] : 0);
    int run  = incl - s;

    for (int i = beg; i < end; i++) {
        rowptr[i] = run;
        run += counts[i];
    }
    if (tid == 1023) rowptr[N_NODES] = run;
}

__global__ void build_csr_kernel(const int* __restrict__ row,
                                 const int* __restrict__ col,
                                 const float* __restrict__ vals,
                                 const int* __restrict__ localoff,
                                 const int* __restrict__ rowptr,
                                 int2* __restrict__ cv) {
    int e = blockIdx.x * blockDim.x + threadIdx.x;
    if (e >= N_EDGES) return;
    int p = __ldg(rowptr + row[e]) + localoff[e];
    cv[p] = make_int2(col[e], __float_as_int(vals[e]));
}

// ---------------------------------------------------------------------------
// Gather SpMM, fp16 feats, FEAT=64: warp per row, lane gathers uint (2 halfs).
// fp32 accumulate, fp16 store.
// ---------------------------------------------------------------------------
__device__ __forceinline__ void fma_h2(float2& acc, float v, unsigned q) {
    __half2 a = *reinterpret_cast<__half2*>(&q);
    float2 f = __half22float2(a);
    acc.x = fmaf(v, f.x, acc.x);
    acc.y = fmaf(v, f.y, acc.y);
}

__global__ void spmm_gather64_h(const int* __restrict__ rowptr,
                                const int2* __restrict__ cv,
                                const __half* __restrict__ H,
                                __half* __restrict__ out) {
    int warp = (blockIdx.x * blockDim.x + threadIdx.x) >> 5;
    int lane = threadIdx.x & 31;
    if (warp >= N_NODES) return;

    int beg = __ldg(rowptr + warp);
    int end = __ldg(rowptr + warp + 1);

    const unsigned* Hu = reinterpret_cast<const unsigned*>(H);
    float2 acc = make_float2(0.f, 0.f);

    int e = beg;
    if ((e & 1) && e < end) {
        int2 p = __ldg(cv + e);
        fma_h2(acc, __int_as_float(p.y), __ldg(Hu + (size_t)p.x * 32 + lane));
        e++;
    }
    const int4* CV4 = reinterpret_cast<const int4*>(cv);
    for (; e + 8 <= end; e += 8) {
        int4 q0 = __ldg(CV4 + (e >> 1) + 0);
        int4 q1 = __ldg(CV4 + (e >> 1) + 1);
        int4 q2 = __ldg(CV4 + (e >> 1) + 2);
        int4 q3 = __ldg(CV4 + (e >> 1) + 3);
        unsigned h0 = __ldg(Hu + (size_t)q0.x * 32 + lane);
        unsigned h1 = __ldg(Hu + (size_t)q0.z * 32 + lane);
        unsigned h2 = __ldg(Hu + (size_t)q1.x * 32 + lane);
        unsigned h3 = __ldg(Hu + (size_t)q1.z * 32 + lane);
        unsigned h4 = __ldg(Hu + (size_t)q2.x * 32 + lane);
        unsigned h5 = __ldg(Hu + (size_t)q2.z * 32 + lane);
        unsigned h6 = __ldg(Hu + (size_t)q3.x * 32 + lane);
        unsigned h7 = __ldg(Hu + (size_t)q3.z * 32 + lane);
        fma_h2(acc, __int_as_float(q0.y), h0);
        fma_h2(acc, __int_as_float(q0.w), h1);
        fma_h2(acc, __int_as_float(q1.y), h2);
        fma_h2(acc, __int_as_float(q1.w), h3);
        fma_h2(acc, __int_as_float(q2.y), h4);
        fma_h2(acc, __int_as_float(q2.w), h5);
        fma_h2(acc, __int_as_float(q3.y), h6);
        fma_h2(acc, __int_as_float(q3.w), h7);
    }
    for (; e + 2 <= end; e += 2) {
        int4 q = __ldg(CV4 + (e >> 1));
        fma_h2(acc, __int_as_float(q.y), __ldg(Hu + (size_t)q.x * 32 + lane));
        fma_h2(acc, __int_as_float(q.w), __ldg(Hu + (size_t)q.z * 32 + lane));
    }
    if (e < end) {
        int2 p = __ldg(cv + e);
        fma_h2(acc, __int_as_float(p.y), __ldg(Hu + (size_t)p.x * 32 + lane));
    }
    __half2 r = __floats2half2_rn(acc.x, acc.y);
    reinterpret_cast<unsigned*>(out)[(size_t)warp * 32 + lane] =
        *reinterpret_cast<unsigned*>(&r);
}

// ---------------------------------------------------------------------------
// Gather SpMM, fp16 feats, FEAT=128: warp per row, lane gathers uint2 (4 halfs).
// fp32 accumulate, fp16 store.
// ---------------------------------------------------------------------------
__device__ __forceinline__ void fma_h4(float4& acc, float v, uint2 q) {
    __half2 a = *reinterpret_cast<__half2*>(&q.x);
    __half2 b = *reinterpret_cast<__half2*>(&q.y);
    float2 fa = __half22float2(a);
    float2 fb = __half22float2(b);
    acc.x = fmaf(v, fa.x, acc.x); acc.y = fmaf(v, fa.y, acc.y);
    acc.z = fmaf(v, fb.x, acc.z); acc.w = fmaf(v, fb.y, acc.w);
}

__global__ void spmm_gather128_h(const int* __restrict__ rowptr,
                                 const int2* __restrict__ cv,
                                 const __half* __restrict__ H,
                                 __half* __restrict__ out) {
    int warp = (blockIdx.x * blockDim.x + threadIdx.x) >> 5;
    int lane = threadIdx.x & 31;
    if (warp >= N_NODES) return;

    int beg = __ldg(rowptr + warp);
    int end = __ldg(rowptr + warp + 1);

    const uint2* Hq = reinterpret_cast<const uint2*>(H);
    float4 acc = make_float4(0.f, 0.f, 0.f, 0.f);

    int e = beg;
    if ((e & 1) && e < end) {
        int2 p = __ldg(cv + e);
        fma_h4(acc, __int_as_float(p.y), __ldg(Hq + (size_t)p.x * 32 + lane));
        e++;
    }
    const int4* CV4 = reinterpret_cast<const int4*>(cv);
    for (; e + 8 <= end; e += 8) {
        int4 q0 = __ldg(CV4 + (e >> 1) + 0);
        int4 q1 = __ldg(CV4 + (e >> 1) + 1);
        int4 q2 = __ldg(CV4 + (e >> 1) + 2);
        int4 q3 = __ldg(CV4 + (e >> 1) + 3);
        uint2 h0 = __ldg(Hq + (size_t)q0.x * 32 + lane);
        uint2 h1 = __ldg(Hq + (size_t)q0.z * 32 + lane);
        uint2 h2 = __ldg(Hq + (size_t)q1.x * 32 + lane);
        uint2 h3 = __ldg(Hq + (size_t)q1.z * 32 + lane);
        uint2 h4 = __ldg(Hq + (size_t)q2.x * 32 + lane);
        uint2 h5 = __ldg(Hq + (size_t)q2.z * 32 + lane);
        uint2 h6 = __ldg(Hq + (size_t)q3.x * 32 + lane);
        uint2 h7 = __ldg(Hq + (size_t)q3.z * 32 + lane);
        fma_h4(acc, __int_as_float(q0.y), h0);
        fma_h4(acc, __int_as_float(q0.w), h1);
        fma_h4(acc, __int_as_float(q1.y), h2);
        fma_h4(acc, __int_as_float(q1.w), h3);
        fma_h4(acc, __int_as_float(q2.y), h4);
        fma_h4(acc, __int_as_float(q2.w), h5);
        fma_h4(acc, __int_as_float(q3.y), h6);
        fma_h4(acc, __int_as_float(q3.w), h7);
    }
    for (; e + 2 <= end; e += 2) {
        int4 q = __ldg(CV4 + (e >> 1));
        fma_h4(acc, __int_as_float(q.y), __ldg(Hq + (size_t)q.x * 32 + lane));
        fma_h4(acc, __int_as_float(q.w), __ldg(Hq + (size_t)q.z * 32 + lane));
    }
    if (e < end) {
        int2 p = __ldg(cv + e);
        fma_h4(acc, __int_as_float(p.y), __ldg(Hq + (size_t)p.x * 32 + lane));
    }
    __half2 lo = __floats2half2_rn(acc.x, acc.y);
    __half2 hi = __floats2half2_rn(acc.z, acc.w);
    uint2 st;
    st.x = *reinterpret_cast<unsigned*>(&lo);
    st.y = *reinterpret_cast<unsigned*>(&hi);
    reinterpret_cast<uint2*>(out)[(size_t)warp * 32 + lane] = st;
}

// ---------------------------------------------------------------------------
// Tensor-core GEMM + bias + ReLU:
//   out[N_NODES,128] = relu(A[N_NODES,K](fp16) @ Wt^T (Wt = [128][K] fp16) + b)
// mma.sync.m16n8k16 f32.f16.f16.f32. Block = 256 thr (8 warps) x 128 rows.
// Smem rows padded to K+8 halfs -> conflict-free scalar LDS fragment loads.
// ---------------------------------------------------------------------------
template <int K, bool HALF_OUT>
__global__ __launch_bounds__(256)
void gemm_tc(const __half* __restrict__ A,
             const __half* __restrict__ Wt,
             const float* __restrict__ bias,
             void* __restrict__ out_) {
    constexpr int SP  = K + 8;          // padded row stride (halfs)
    constexpr int CPR = K / 8;          // uint4 chunks per row

    extern __shared__ __half sm[];
    __half* As  = sm;                   // 128 x SP
    __half* Wts = sm + 128 * SP;        // 128 x SP

    const int tid  = threadIdx.x;
    const int row0 = blockIdx.x * 128;

    // stage A tile (128 rows x K halfs), zero-pad OOB rows
    {
        const uint4* A4 = reinterpret_cast<const uint4*>(A);
        #pragma unroll
        for (int i = tid; i < 128 * CPR; i += 256) {
            int r = i / CPR, c = i % CPR;
            uint4 v = make_uint4(0u, 0u, 0u, 0u);
            if (row0 + r < N_NODES) v = __ldg(A4 + (size_t)(row0 + r) * CPR + c);
            *reinterpret_cast<uint4*>(As + r * SP + c * 8) = v;
        }
    }
    // stage Wt (128 x K halfs)
    {
        const uint4* W4 = reinterpret_cast<const uint4*>(Wt);
        #pragma unroll
        for (int i = tid; i < 128 * CPR; i += 256) {
            int r = i / CPR, c = i % CPR;
            *reinterpret_cast<uint4*>(Wts + r * SP + c * 8) = __ldg(W4 + i);
        }
    }
    __syncthreads();

    const int warp = tid >> 5;
    const int lane = tid & 31;
    const int gid  = lane >> 2;         // 0..7
    const int q    = lane & 3;          // 0..3
    const int m0   = warp * 16;         // warp's row offset in tile

    // accumulators: 16 n-tiles x 4 floats, bias-initialized
    float acc[16][4];
    #pragma unroll
    for (int t = 0; t < 16; t++) {
        float bx = __ldg(bias + t * 8 + 2 * q);
        float by = __ldg(bias + t * 8 + 2 * q + 1);
        acc[t][0] = bx; acc[t][1] = by;
        acc[t][2] = bx; acc[t][3] = by;
    }

    #pragma unroll
    for (int ks = 0; ks < K / 16; ks++) {
        const int k0 = ks * 16;
        unsigned a0 = *reinterpret_cast<const unsigned*>(As + (m0 + gid)     * SP + k0 + 2 * q);
        unsigned a1 = *reinterpret_cast<const unsigned*>(As + (m0 + gid + 8) * SP + k0 + 2 * q);
        unsigned a2 = *reinterpret_cast<const unsigned*>(As + (m0 + gid)     * SP + k0 + 2 * q + 8);
        unsigned a3 = *reinterpret_cast<const unsigned*>(As + (m0 + gid + 8) * SP + k0 + 2 * q + 8);
        #pragma unroll
        for (int t = 0; t < 16; t++) {
            unsigned b0 = *reinterpret_cast<const unsigned*>(Wts + (t * 8 + gid) * SP + k0 + 2 * q);
            unsigned b1 = *reinterpret_cast<const unsigned*>(Wts + (t * 8 + gid) * SP + k0 + 2 * q + 8);
            asm volatile(
                "mma.sync.aligned.m16n8k16.row.col.f32.f16.f16.f32 "
                "{%0,%1,%2,%3}, {%4,%5,%6,%7}, {%8,%9}, {%0,%1,%2,%3};"
                : "+f"(acc[t][0]), "+f"(acc[t][1]), "+f"(acc[t][2]), "+f"(acc[t][3])
                : "r"(a0), "r"(a1), "r"(a2), "r"(a3), "r"(b0), "r"(b1));
        }
    }

    // epilogue: relu + store
    const int r1 = row0 + m0 + gid;
    const int r2 = r1 + 8;
    #pragma unroll
    for (int t = 0; t < 16; t++) {
        int ccol = t * 8 + 2 * q;
        float x0 = fmaxf(acc[t][0], 0.f), y0 = fmaxf(acc[t][1], 0.f);
        float x1 = fmaxf(acc[t][2], 0.f), y1 = fmaxf(acc[t][3], 0.f);
        if (HALF_OUT) {
            __half* o = (__half*)out_;
            if (r1 < N_NODES) {
                __half2 h = __floats2half2_rn(x0, y0);
                *reinterpret_cast<unsigned*>(o + (size_t)r1 * 128 + ccol) =
                    *reinterpret_cast<unsigned*>(&h);
            }
            if (r2 < N_NODES) {
                __half2 h = __floats2half2_rn(x1, y1);
                *reinterpret_cast<unsigned*>(o + (size_t)r2 * 128 + ccol) =
                    *reinterpret_cast<unsigned*>(&h);
            }
        } else {
            float* o = (float*)out_;
            if (r1 < N_NODES)
                *reinterpret_cast<float2*>(o + (size_t)r1 * 128 + ccol) = make_float2(x0, y0);
            if (r2 < N_NODES)
                *reinterpret_cast<float2*>(o + (size_t)r2 * 128 + ccol) = make_float2(x1, y1);
        }
    }
}

// ---------------------------------------------------------------------------
// launch
// ---------------------------------------------------------------------------
extern "C" void kernel_launch(void* const* d_in, const int* in_sizes, int n_in,
                              void* d_out, int out_size) {
    const int*   row  = (const int*)  d_in[0];
    const int*   col  = (const int*)  d_in[1];
    const float* vals = (const float*)d_in[2];
    const float* H    = (const float*)d_in[3];
    const float* W1   = (const float*)d_in[4];
    const float* b1   = (const float*)d_in[5];
    const float* W2   = (const float*)d_in[6];
    const float* b2   = (const float*)d_in[7];
    float* out = (float*)d_out;

    void *pHh_, *pAHh_, *pH1_, *pAH1_, *pW1t_, *pW2t_, *pCnt_, *pRp_, *pLo_, *pCv_;
    cudaGetSymbolAddress(&pHh_,  g_Hh);
    cudaGetSymbolAddress(&pAHh_, g_AHh);
    cudaGetSymbolAddress(&pH1_,  g_H1h);
    cudaGetSymbolAddress(&pAH1_, g_AH1h);
    cudaGetSymbolAddress(&pW1t_, g_W1t);
    cudaGetSymbolAddress(&pW2t_, g_W2t);
    cudaGetSymbolAddress(&pCnt_, g_counts);
    cudaGetSymbolAddress(&pRp_,  g_rowptr);
    cudaGetSymbolAddress(&pLo_,  g_localoff);
    cudaGetSymbolAddress(&pCv_,  g_csr_cv);
    __half* pHh  = (__half*)pHh_;
    __half* pAHh = (__half*)pAHh_;
    __half* pH1  = (__half*)pH1_;
    __half* pAH1 = (__half*)pAH1_;
    __half* pW1t = (__half*)pW1t_;
    __half* pW2t = (__half*)pW2t_;
    int*    pCnt = (int*)pCnt_;
    int*    pRp  = (int*)pRp_;
    int*    pLo  = (int*)pLo_;
    int2*   pCv  = (int2*)pCv_;

    const int smem64  = 2 * 128 * (64 + 8)  * (int)sizeof(__half);   // 36.9 KB
    const int smem128 = 2 * 128 * (128 + 8) * (int)sizeof(__half);   // 69.6 KB
    cudaFuncSetAttribute(gemm_tc<64, true>,
                         cudaFuncAttributeMaxDynamicSharedMemorySize, smem64);
    cudaFuncSetAttribute(gemm_tc<128, false>,
                         cudaFuncAttributeMaxDynamicSharedMemorySize, smem128);

    // ---- prep (independent of CSR build)
    prep_h_kernel<<<(N_NODES * D_FEAT / 2 + 255) / 256, 256>>>(H, pHh);
    prep_wt_kernel<64, 128><<<(64 * 128 + 255) / 256, 256>>>(W1, pW1t);
    prep_wt_kernel<128, 128><<<(128 * 128 + 255) / 256, 256>>>(W2, pW2t);

    // ---- CSR build
    cudaMemsetAsync(pCnt, 0, N_NODES * sizeof(int));
    hist_off_kernel<<<(N_EDGES + 255) / 256, 256>>>(row, pCnt, pLo);
    scan_kernel<<<1, 1024>>>(pCnt, pRp);
    build_csr_kernel<<<(N_EDGES + 255) / 256, 256>>>(row, col, vals, pLo, pRp, pCv);

    const int warps_grid = (N_NODES * 32 + 255) / 256;   // 1 warp per row
    const int gblocks    = (N_NODES + 127) / 128;

    // ---- layer 0: AH = A@H (fp16 gather); H1 = relu(AH@W1+b1) fp16
    spmm_gather64_h<<<warps_grid, 256>>>(pRp, pCv, pHh, pAHh);
    gemm_tc<64, true><<<gblocks, 256, smem64>>>(pAHh, pW1t, b1, pH1);

    // ---- layer 1: AH1 = A@H1 (fp16 gather); out = relu(AH1@W2+b2) fp32
    spmm_gather128_h<<<warps_grid, 256>>>(pRp, pCv, pH1, pAH1);
    gemm_tc<128, false><<<gblocks, 256, smem128>>>(pAH1, pW2t, b2, out);
}

// round 7
// speedup vs baseline: 1.6595x; 1.0064x over previous
#include <cuda_runtime.h>
#include <cuda_bf16.h>
#include <cuda_fp16.h>
#include <cstdint>

#define N_NODES 100000
#define N_EDGES 1600000
#define D_FEAT  64
#define U1      128
#define U2      128

// ---------------------------------------------------------------------------
// Scratch (allocation-free rule: __device__ globals)
// ---------------------------------------------------------------------------
__device__ __half g_Hh  [(size_t)N_NODES * D_FEAT];  // 12.8 MB  fp16 input feats
__device__ __half g_AHh [(size_t)N_NODES * D_FEAT];  // 12.8 MB  fp16 A@H
__device__ __half g_H1h [(size_t)N_NODES * U1];      // 25.6 MB  fp16 layer-1 feats
__device__ __half g_AH1h[(size_t)N_NODES * U1];      // 25.6 MB  fp16 A@H1
__device__ __half g_W1t [U1 * D_FEAT];               // W1^T  [n][k] fp16
__device__ __half g_W2t [U2 * U1];                   // W2^T  [n][k] fp16
__device__ int    g_counts[N_NODES];
__device__ int    g_rowptr[N_NODES + 1];
__device__ int    g_localoff[N_EDGES];
__device__ int4   g_csr_cv[N_EDGES / 2];             // packed (col,val) 12.8 MB

// ---------------------------------------------------------------------------
// prep: H fp32 -> fp16 ; W transpose+convert
// ---------------------------------------------------------------------------
__global__ void prep_h_kernel(const float* __restrict__ H, __half* __restrict__ Hh) {
    int i = blockIdx.x * blockDim.x + threadIdx.x;          // over N*64/2
    if (i < N_NODES * D_FEAT / 2) {
        float2 f = reinterpret_cast<const float2*>(H)[i];
        reinterpret_cast<__half2*>(Hh)[i] = __floats2half2_rn(f.x, f.y);
    }
}

template <int K, int N>
__global__ void prep_wt_kernel(const float* __restrict__ W, __half* __restrict__ Wt) {
    int i = blockIdx.x * blockDim.x + threadIdx.x;          // over K*N
    if (i < K * N) {
        int k = i / N, n = i % N;
        Wt[n * K + k] = __float2half(W[i]);
    }
}

// ---------------------------------------------------------------------------
// CSR build
// ---------------------------------------------------------------------------
__global__ void hist_off_kernel(const int* __restrict__ row,
                                int* __restrict__ counts,
                                int* __restrict__ localoff) {
    int e = blockIdx.x * blockDim.x + threadIdx.x;
    if (e < N_EDGES) localoff[e] = atomicAdd(&counts[row[e]], 1);
}

__global__ void scan_kernel(const int* __restrict__ counts,
                            int* __restrict__ rowptr) {
    const int tid  = threadIdx.x;
    const int lane = tid & 31;
    const int wid  = tid >> 5;
    const int CH   = (N_NODES + 1023) / 1024;
    int beg = tid * CH;
    int end = beg + CH; if (end > N_NODES) end = N_NODES;
    if (beg > N_NODES) beg = N_NODES;

    int s = 0;
    for (int i = beg; i < end; i++) s += counts[i];

    int v = s;
    #pragma unroll
    for (int o = 1; o < 32; o <<= 1) {
        int t = __shfl_up_sync(0xFFFFFFFFu, v, o);
        if (lane >= o) v += t;
    }
    __shared__ int wsum[32];
    if (lane == 31) wsum[wid] = v;
    __syncthreads();
    if (wid == 0) {
        int x = wsum[lane];
        #pragma unroll
        for (int o = 1; o < 32; o <<= 1) {
            int t = __shfl_up_sync(0xFFFFFFFFu, x, o);
            if (lane >= o) x += t;
        }
        wsum[lane] = x;
    }
    __syncthreads();
    int incl = v + (wid > 0 ? wsum[wid - 1] : 0);
    int run  = incl - s;

    for (int i = beg; i < end; i++) {
        rowptr[i] = run;
        run += counts[i];
    }
    if (tid == 1023) rowptr[N_NODES] = run;
}

__global__ void build_csr_kernel(const int* __restrict__ row,
                                 const int* __restrict__ col,
                                 const float* __restrict__ vals,
                                 const int* __restrict__ localoff,
                                 const int* __restrict__ rowptr,
                                 int2* __restrict__ cv) {
    int e = blockIdx.x * blockDim.x + threadIdx.x;
    if (e >= N_EDGES) return;
    int p = __ldg(rowptr + row[e]) + localoff[e];
    cv[p] = make_int2(col[e], __float_as_int(vals[e]));
}

// ---------------------------------------------------------------------------
// Gather SpMM, fp16 feats, FEAT=64: warp per row, lane gathers uint (2 halfs).
// fp32 accumulate, fp16 store.
// ---------------------------------------------------------------------------
__device__ __forceinline__ void fma_h2(float2& acc, float v, unsigned q) {
    __half2 a = *reinterpret_cast<__half2*>(&q);
    float2 f = __half22float2(a);
    acc.x = fmaf(v, f.x, acc.x);
    acc.y = fmaf(v, f.y, acc.y);
}

__global__ void spmm_gather64_h(const int* __restrict__ rowptr,
                                const int2* __restrict__ cv,
                                const __half* __restrict__ H,
                                __half* __restrict__ out) {
    int warp = (blockIdx.x * blockDim.x + threadIdx.x) >> 5;
    int lane = threadIdx.x & 31;
    if (warp >= N_NODES) return;

    int beg = __ldg(rowptr + warp);
    int end = __ldg(rowptr + warp + 1);

    const unsigned* Hu = reinterpret_cast<const unsigned*>(H);
    float2 acc = make_float2(0.f, 0.f);

    int e = beg;
    if ((e & 1) && e < end) {
        int2 p = __ldg(cv + e);
        fma_h2(acc, __int_as_float(p.y), __ldg(Hu + (size_t)p.x * 32 + lane));
        e++;
    }
    const int4* CV4 = reinterpret_cast<const int4*>(cv);
    for (; e + 8 <= end; e += 8) {
        int4 q0 = __ldg(CV4 + (e >> 1) + 0);
        int4 q1 = __ldg(CV4 + (e >> 1) + 1);
        int4 q2 = __ldg(CV4 + (e >> 1) + 2);
        int4 q3 = __ldg(CV4 + (e >> 1) + 3);
        unsigned h0 = __ldg(Hu + (size_t)q0.x * 32 + lane);
        unsigned h1 = __ldg(Hu + (size_t)q0.z * 32 + lane);
        unsigned h2 = __ldg(Hu + (size_t)q1.x * 32 + lane);
        unsigned h3 = __ldg(Hu + (size_t)q1.z * 32 + lane);
        unsigned h4 = __ldg(Hu + (size_t)q2.x * 32 + lane);
        unsigned h5 = __ldg(Hu + (size_t)q2.z * 32 + lane);
        unsigned h6 = __ldg(Hu + (size_t)q3.x * 32 + lane);
        unsigned h7 = __ldg(Hu + (size_t)q3.z * 32 + lane);
        fma_h2(acc, __int_as_float(q0.y), h0);
        fma_h2(acc, __int_as_float(q0.w), h1);
        fma_h2(acc, __int_as_float(q1.y), h2);
        fma_h2(acc, __int_as_float(q1.w), h3);
        fma_h2(acc, __int_as_float(q2.y), h4);
        fma_h2(acc, __int_as_float(q2.w), h5);
        fma_h2(acc, __int_as_float(q3.y), h6);
        fma_h2(acc, __int_as_float(q3.w), h7);
    }
    for (; e + 2 <= end; e += 2) {
        int4 q = __ldg(CV4 + (e >> 1));
        fma_h2(acc, __int_as_float(q.y), __ldg(Hu + (size_t)q.x * 32 + lane));
        fma_h2(acc, __int_as_float(q.w), __ldg(Hu + (size_t)q.z * 32 + lane));
    }
    if (e < end) {
        int2 p = __ldg(cv + e);
        fma_h2(acc, __int_as_float(p.y), __ldg(Hu + (size_t)p.x * 32 + lane));
    }
    __half2 r = __floats2half2_rn(acc.x, acc.y);
    reinterpret_cast<unsigned*>(out)[(size_t)warp * 32 + lane] =
        *reinterpret_cast<unsigned*>(&r);
}

// ---------------------------------------------------------------------------
// Gather SpMM, fp16 feats, FEAT=128: warp per row, lane gathers uint2 (4 halfs).
// fp32 accumulate, fp16 store.
// ---------------------------------------------------------------------------
__device__ __forceinline__ void fma_h4(float4& acc, float v, uint2 q) {
    __half2 a = *reinterpret_cast<__half2*>(&q.x);
    __half2 b = *reinterpret_cast<__half2*>(&q.y);
    float2 fa = __half22float2(a);
    float2 fb = __half22float2(b);
    acc.x = fmaf(v, fa.x, acc.x); acc.y = fmaf(v, fa.y, acc.y);
    acc.z = fmaf(v, fb.x, acc.z); acc.w = fmaf(v, fb.y, acc.w);
}

__global__ void spmm_gather128_h(const int* __restrict__ rowptr,
                                 const int2* __restrict__ cv,
                                 const __half* __restrict__ H,
                                 __half* __restrict__ out) {
    int warp = (blockIdx.x * blockDim.x + threadIdx.x) >> 5;
    int lane = threadIdx.x & 31;
    if (warp >= N_NODES) return;

    int beg = __ldg(rowptr + warp);
    int end = __ldg(rowptr + warp + 1);

    const uint2* Hq = reinterpret_cast<const uint2*>(H);
    float4 acc = make_float4(0.f, 0.f, 0.f, 0.f);

    int e = beg;
    if ((e & 1) && e < end) {
        int2 p = __ldg(cv + e);
        fma_h4(acc, __int_as_float(p.y), __ldg(Hq + (size_t)p.x * 32 + lane));
        e++;
    }
    const int4* CV4 = reinterpret_cast<const int4*>(cv);
    for (; e + 8 <= end; e += 8) {
        int4 q0 = __ldg(CV4 + (e >> 1) + 0);
        int4 q1 = __ldg(CV4 + (e >> 1) + 1);
        int4 q2 = __ldg(CV4 + (e >> 1) + 2);
        int4 q3 = __ldg(CV4 + (e >> 1) + 3);
        uint2 h0 = __ldg(Hq + (size_t)q0.x * 32 + lane);
        uint2 h1 = __ldg(Hq + (size_t)q0.z * 32 + lane);
        uint2 h2 = __ldg(Hq + (size_t)q1.x * 32 + lane);
        uint2 h3 = __ldg(Hq + (size_t)q1.z * 32 + lane);
        uint2 h4 = __ldg(Hq + (size_t)q2.x * 32 + lane);
        uint2 h5 = __ldg(Hq + (size_t)q2.z * 32 + lane);
        uint2 h6 = __ldg(Hq + (size_t)q3.x * 32 + lane);
        uint2 h7 = __ldg(Hq + (size_t)q3.z * 32 + lane);
        fma_h4(acc, __int_as_float(q0.y), h0);
        fma_h4(acc, __int_as_float(q0.w), h1);
        fma_h4(acc, __int_as_float(q1.y), h2);
        fma_h4(acc, __int_as_float(q1.w), h3);
        fma_h4(acc, __int_as_float(q2.y), h4);
        fma_h4(acc, __int_as_float(q2.w), h5);
        fma_h4(acc, __int_as_float(q3.y), h6);
        fma_h4(acc, __int_as_float(q3.w), h7);
    }
    for (; e + 2 <= end; e += 2) {
        int4 q = __ldg(CV4 + (e >> 1));
        fma_h4(acc, __int_as_float(q.y), __ldg(Hq + (size_t)q.x * 32 + lane));
        fma_h4(acc, __int_as_float(q.w), __ldg(Hq + (size_t)q.z * 32 + lane));
    }
    if (e < end) {
        int2 p = __ldg(cv + e);
        fma_h4(acc, __int_as_float(p.y), __ldg(Hq + (size_t)p.x * 32 + lane));
    }
    __half2 lo = __floats2half2_rn(acc.x, acc.y);
    __half2 hi = __floats2half2_rn(acc.z, acc.w);
    uint2 st;
    st.x = *reinterpret_cast<unsigned*>(&lo);
    st.y = *reinterpret_cast<unsigned*>(&hi);
    reinterpret_cast<uint2*>(out)[(size_t)warp * 32 + lane] = st;
}

// ---------------------------------------------------------------------------
// Tensor-core GEMM + bias + ReLU:
//   out[N_NODES,128] = relu(A[N_NODES,K](fp16) @ Wt^T (Wt = [128][K] fp16) + b)
// mma.sync.m16n8k16 f32.f16.f16.f32. Block = 256 thr (8 warps) x 128 rows.
// Smem rows padded to K+8 halfs -> conflict-free scalar LDS fragment loads.
// ---------------------------------------------------------------------------
template <int K, bool HALF_OUT>
__global__ __launch_bounds__(256)
void gemm_tc(const __half* __restrict__ A,
             const __half* __restrict__ Wt,
             const float* __restrict__ bias,
             void* __restrict__ out_) {
    constexpr int SP  = K + 8;          // padded row stride (halfs)
    constexpr int CPR = K / 8;          // uint4 chunks per row

    extern __shared__ __half sm[];
    __half* As  = sm;                   // 128 x SP
    __half* Wts = sm + 128 * SP;        // 128 x SP

    const int tid  = threadIdx.x;
    const int row0 = blockIdx.x * 128;

    // stage A tile (128 rows x K halfs), zero-pad OOB rows
    {
        const uint4* A4 = reinterpret_cast<const uint4*>(A);
        #pragma unroll
        for (int i = tid; i < 128 * CPR; i += 256) {
            int r = i / CPR, c = i % CPR;
            uint4 v = make_uint4(0u, 0u, 0u, 0u);
            if (row0 + r < N_NODES) v = __ldg(A4 + (size_t)(row0 + r) * CPR + c);
            *reinterpret_cast<uint4*>(As + r * SP + c * 8) = v;
        }
    }
    // stage Wt (128 x K halfs)
    {
        const uint4* W4 = reinterpret_cast<const uint4*>(Wt);
        #pragma unroll
        for (int i = tid; i < 128 * CPR; i += 256) {
            int r = i / CPR, c = i % CPR;
            *reinterpret_cast<uint4*>(Wts + r * SP + c * 8) = __ldg(W4 + i);
        }
    }
    __syncthreads();

    const int warp = tid >> 5;
    const int lane = tid & 31;
    const int gid  = lane >> 2;         // 0..7
    const int q    = lane & 3;          // 0..3
    const int m0   = warp * 16;         // warp's row offset in tile

    // accumulators: 16 n-tiles x 4 floats, bias-initialized
    float acc[16][4];
    #pragma unroll
    for (int t = 0; t < 16; t++) {
        float bx = __ldg(bias + t * 8 + 2 * q);
        float by = __ldg(bias + t * 8 + 2 * q + 1);
        acc[t][0] = bx; acc[t][1] = by;
        acc[t][2] = bx; acc[t][3] = by;
    }

    #pragma unroll
    for (int ks = 0; ks < K / 16; ks++) {
        const int k0 = ks * 16;
        unsigned a0 = *reinterpret_cast<const unsigned*>(As + (m0 + gid)     * SP + k0 + 2 * q);
        unsigned a1 = *reinterpret_cast<const unsigned*>(As + (m0 + gid + 8) * SP + k0 + 2 * q);
        unsigned a2 = *reinterpret_cast<const unsigned*>(As + (m0 + gid)     * SP + k0 + 2 * q + 8);
        unsigned a3 = *reinterpret_cast<const unsigned*>(As + (m0 + gid + 8) * SP + k0 + 2 * q + 8);
        #pragma unroll
        for (int t = 0; t < 16; t++) {
            unsigned b0 = *reinterpret_cast<const unsigned*>(Wts + (t * 8 + gid) * SP + k0 + 2 * q);
            unsigned b1 = *reinterpret_cast<const unsigned*>(Wts + (t * 8 + gid) * SP + k0 + 2 * q + 8);
            asm volatile(
                "mma.sync.aligned.m16n8k16.row.col.f32.f16.f16.f32 "
                "{%0,%1,%2,%3}, {%4,%5,%6,%7}, {%8,%9}, {%0,%1,%2,%3};"
                : "+f"(acc[t][0]), "+f"(acc[t][1]), "+f"(acc[t][2]), "+f"(acc[t][3])
                : "r"(a0), "r"(a1), "r"(a2), "r"(a3), "r"(b0), "r"(b1));
        }
    }

    // epilogue: relu + store
    const int r1 = row0 + m0 + gid;
    const int r2 = r1 + 8;
    #pragma unroll
    for (int t = 0; t < 16; t++) {
        int ccol = t * 8 + 2 * q;
        float x0 = fmaxf(acc[t][0], 0.f), y0 = fmaxf(acc[t][1], 0.f);
        float x1 = fmaxf(acc[t][2], 0.f), y1 = fmaxf(acc[t][3], 0.f);
        if (HALF_OUT) {
            __half* o = (__half*)out_;
            if (r1 < N_NODES) {
                __half2 h = __floats2half2_rn(x0, y0);
                *reinterpret_cast<unsigned*>(o + (size_t)r1 * 128 + ccol) =
                    *reinterpret_cast<unsigned*>(&h);
            }
            if (r2 < N_NODES) {
                __half2 h = __floats2half2_rn(x1, y1);
                *reinterpret_cast<unsigned*>(o + (size_t)r2 * 128 + ccol) =
                    *reinterpret_cast<unsigned*>(&h);
            }
        } else {
            float* o = (float*)out_;
            if (r1 < N_NODES)
                *reinterpret_cast<float2*>(o + (size_t)r1 * 128 + ccol) = make_float2(x0, y0);
            if (r2 < N_NODES)
                *reinterpret_cast<float2*>(o + (size_t)r2 * 128 + ccol) = make_float2(x1, y1);
        }
    }
}

// ---------------------------------------------------------------------------
// launch
// ---------------------------------------------------------------------------
extern "C" void kernel_launch(void* const* d_in, const int* in_sizes, int n_in,
                              void* d_out, int out_size) {
    const int*   row  = (const int*)  d_in[0];
    const int*   col  = (const int*)  d_in[1];
    const float* vals = (const float*)d_in[2];
    const float* H    = (const float*)d_in[3];
    const float* W1   = (const float*)d_in[4];
    const float* b1   = (const float*)d_in[5];
    const float* W2   = (const float*)d_in[6];
    const float* b2   = (const float*)d_in[7];
    float* out = (float*)d_out;

    void *pHh_, *pAHh_, *pH1_, *pAH1_, *pW1t_, *pW2t_, *pCnt_, *pRp_, *pLo_, *pCv_;
    cudaGetSymbolAddress(&pHh_,  g_Hh);
    cudaGetSymbolAddress(&pAHh_, g_AHh);
    cudaGetSymbolAddress(&pH1_,  g_H1h);
    cudaGetSymbolAddress(&pAH1_, g_AH1h);
    cudaGetSymbolAddress(&pW1t_, g_W1t);
    cudaGetSymbolAddress(&pW2t_, g_W2t);
    cudaGetSymbolAddress(&pCnt_, g_counts);
    cudaGetSymbolAddress(&pRp_,  g_rowptr);
    cudaGetSymbolAddress(&pLo_,  g_localoff);
    cudaGetSymbolAddress(&pCv_,  g_csr_cv);
    __half* pHh  = (__half*)pHh_;
    __half* pAHh = (__half*)pAHh_;
    __half* pH1  = (__half*)pH1_;
    __half* pAH1 = (__half*)pAH1_;
    __half* pW1t = (__half*)pW1t_;
    __half* pW2t = (__half*)pW2t_;
    int*    pCnt = (int*)pCnt_;
    int*    pRp  = (int*)pRp_;
    int*    pLo  = (int*)pLo_;
    int2*   pCv  = (int2*)pCv_;

    const int smem64  = 2 * 128 * (64 + 8)  * (int)sizeof(__half);   // 36.9 KB
    const int smem128 = 2 * 128 * (128 + 8) * (int)sizeof(__half);   // 69.6 KB
    cudaFuncSetAttribute(gemm_tc<64, true>,
                         cudaFuncAttributeMaxDynamicSharedMemorySize, smem64);
    cudaFuncSetAttribute(gemm_tc<128, false>,
                         cudaFuncAttributeMaxDynamicSharedMemorySize, smem128);

    // ---- prep (independent of CSR build)
    prep_h_kernel<<<(N_NODES * D_FEAT / 2 + 255) / 256, 256>>>(H, pHh);
    prep_wt_kernel<64, 128><<<(64 * 128 + 255) / 256, 256>>>(W1, pW1t);
    prep_wt_kernel<128, 128><<<(128 * 128 + 255) / 256, 256>>>(W2, pW2t);

    // ---- CSR build
    cudaMemsetAsync(pCnt, 0, N_NODES * sizeof(int));
    hist_off_kernel<<<(N_EDGES + 255) / 256, 256>>>(row, pCnt, pLo);
    scan_kernel<<<1, 1024>>>(pCnt, pRp);
    build_csr_kernel<<<(N_EDGES + 255) / 256, 256>>>(row, col, vals, pLo, pRp, pCv);

    const int warps_grid = (N_NODES * 32 + 255) / 256;   // 1 warp per row
    const int gblocks    = (N_NODES + 127) / 128;

    // ---- layer 0: AH = A@H (fp16 gather); H1 = relu(AH@W1+b1) fp16
    spmm_gather64_h<<<warps_grid, 256>>>(pRp, pCv, pHh, pAHh);
    gemm_tc<64, true><<<gblocks, 256, smem64>>>(pAHh, pW1t, b1, pH1);

    // ---- layer 1: AH1 = A@H1 (fp16 gather); out = relu(AH1@W2+b2) fp32
    spmm_gather128_h<<<warps_grid, 256>>>(pRp, pCv, pH1, pAH1);
    gemm_tc<128, false><<<gblocks, 256, smem128>>>(pAH1, pW2t, b2, out);
}